// round 6
// baseline (speedup 1.0000x reference)
#include <cuda_runtime.h>
#include <cuda_bf16.h>
#include <cstring>
#include <cstdint>

#define NN 50000
#define EE 400000
#define NHEAD 8
#define DEF 16
#define DNF 16

// ---------------- device global scratch ------------------------------------
__device__ float g_N1t[128 * 128];   // (W1@W_ni)^T: [k][c]
__device__ float g_A2t[128 * 128];   // (W2@W_fij)^T
__device__ float g_N3t[128 * 128];   // (W3@W_nj)^T
__device__ float g_Wnt[128 * 128];   // W_node^T
__device__ float g_wsum[DEF];
// B operands as bf16 [n][k], row stride 136 elements
__device__ __nv_bfloat16 g_Bhi[4 * 128 * 136];
__device__ __nv_bfloat16 g_Blo[4 * 128 * 136];
__device__ float g_tsrc[NN * 128];
__device__ float g_tdst[NN * 128];
__device__ float g_hnode[NN * 128];
__device__ float g_a[EE * NHEAD];    // exp(logit) * norm
__device__ float g_den[NN * NHEAD];  // sum of raw exp(logit)

// ---------------- smem layout (bytes) ---------------------------------------
#define RSTRIDE 272                  // 136 bf16 per row
#define AB_BYTES (128 * RSTRIDE)     // 34816 per operand buffer
#define SM_BIAS 0
#define SM_WS   512
#define SM_AHI  1024
#define SM_ALO  (SM_AHI + AB_BYTES)      // 35840
#define SM_BHI  (SM_ALO + AB_BYTES)      // 70656
#define SM_BLO  (SM_BHI + AB_BYTES)      // 105472
#define SM_FB   (SM_BLO + AB_BYTES)      // 140288
#define FB_STRIDE 132
#define SM_TOTAL (SM_FB + 128 * FB_STRIDE * 4)   // 207872

// ---------------- small kernels ----------------------------------------------
__global__ void k_init(float* __restrict__ out1) {
    int i = blockIdx.x * blockDim.x + threadIdx.x;
    if (i < NN * NHEAD) g_den[i] = 0.f;
    if (i < NN * DNF)   out1[i] = 0.f;
}

__global__ void k_weights(const float* __restrict__ W_edges,
                          const float* __restrict__ W_ni,
                          const float* __restrict__ W_nj,
                          const float* __restrict__ W_fij,
                          const float* __restrict__ W_node,
                          const float* __restrict__ W_attn) {
    int k = blockIdx.x, c = threadIdx.x, m = blockIdx.y;
    if (m == 0) {
        float acc = 0.f;
        for (int j = 0; j < 128; ++j) acc += W_edges[c * 384 + j] * W_ni[j * 128 + k];
        g_N1t[k * 128 + c] = acc;
    } else if (m == 1) {
        float acc = 0.f;
        for (int j = 0; j < 128; ++j) acc += W_edges[c * 384 + 128 + j] * W_fij[j * 128 + k];
        g_A2t[k * 128 + c] = acc;
    } else if (m == 2) {
        float acc = 0.f;
        for (int j = 0; j < 128; ++j) acc += W_edges[c * 384 + 256 + j] * W_nj[j * 128 + k];
        g_N3t[k * 128 + c] = acc;
    } else {
        g_Wnt[k * 128 + c] = W_node[c * 128 + k];
        if (k == 0 && c < DEF) {
            float s = 0.f;
            for (int h = 0; h < NHEAD; ++h) s += W_attn[h * DEF + c];
            g_wsum[c] = s;
        }
    }
}

__global__ void k_wconv() {
    int idx = blockIdx.x * blockDim.x + threadIdx.x;  // 65536
    int m = idx >> 14, r = idx & 16383;
    int n = r >> 7, k = r & 127;                      // B[n][k] = Wt[k][n]
    const float* srcs[4] = {g_N1t, g_A2t, g_N3t, g_Wnt};
    float w = srcs[m][k * 128 + n];
    __nv_bfloat16 h = __float2bfloat16(w);
    __nv_bfloat16 l = __float2bfloat16(w - __bfloat162float(h));
    g_Bhi[m * 128 * 136 + n * 136 + k] = h;
    g_Blo[m * 128 * 136 + n * 136 + k] = l;
}

// ---------------- helpers -----------------------------------------------------
__device__ __forceinline__ uint32_t smem_u32(const void* p) {
    uint32_t a;
    asm("{ .reg .u64 t; cvta.to.shared.u64 t, %1; cvt.u32.u64 %0, t; }" : "=r"(a) : "l"(p));
    return a;
}

__device__ __forceinline__ void split8(const float4 v0, const float4 v1, uint4& H, uint4& L) {
    float x[8] = {v0.x, v0.y, v0.z, v0.w, v1.x, v1.y, v1.z, v1.w};
    unsigned hu[4], lu[4];
#pragma unroll
    for (int j = 0; j < 4; ++j) {
        __nv_bfloat162 hp = __floats2bfloat162_rn(x[2 * j], x[2 * j + 1]);
        float ra = x[2 * j]     - __low2float(hp);
        float rb = x[2 * j + 1] - __high2float(hp);
        __nv_bfloat162 lp = __floats2bfloat162_rn(ra, rb);
        memcpy(&hu[j], &hp, 4);
        memcpy(&lu[j], &lp, 4);
    }
    H = make_uint4(hu[0], hu[1], hu[2], hu[3]);
    L = make_uint4(lu[0], lu[1], lu[2], lu[3]);
}

// prefetch a 128x128 fp32 tile into registers
__device__ __forceinline__ void prefetch_tile(float4 (&pf)[16], const float* __restrict__ srcp,
                                              int base, int limit, int t) {
#pragma unroll
    for (int j = 0; j < 8; ++j) {
        int i = t + j * 256;
        int row = i >> 4, col = (i & 15) * 8;
        int gr = base + row;
        if (gr < limit) {
            pf[2 * j]     = __ldg((const float4*)(srcp + (size_t)gr * 128 + col));
            pf[2 * j + 1] = __ldg((const float4*)(srcp + (size_t)gr * 128 + col + 4));
        } else {
            pf[2 * j] = make_float4(0.f, 0.f, 0.f, 0.f);
            pf[2 * j + 1] = pf[2 * j];
        }
    }
}

// convert prefetched registers into bf16 hi/lo smem
__device__ __forceinline__ void sts_tile(char* smc, const float4 (&pf)[16], int t) {
#pragma unroll
    for (int j = 0; j < 8; ++j) {
        int i = t + j * 256;
        int row = i >> 4, col = (i & 15) * 8;
        uint4 H, L;
        split8(pf[2 * j], pf[2 * j + 1], H, L);
        *(uint4*)(smc + SM_AHI + row * RSTRIDE + col * 2) = H;
        *(uint4*)(smc + SM_ALO + row * RSTRIDE + col * 2) = L;
    }
}

// ---------------- mma core -----------------------------------------------------
__device__ __forceinline__ void mma16816(float (&d)[4], const uint32_t (&a)[4],
                                         uint32_t b0, uint32_t b1) {
    asm("mma.sync.aligned.m16n8k16.row.col.f32.bf16.bf16.f32 "
        "{%0,%1,%2,%3}, {%4,%5,%6,%7}, {%8,%9}, {%0,%1,%2,%3};"
        : "+f"(d[0]), "+f"(d[1]), "+f"(d[2]), "+f"(d[3])
        : "r"(a[0]), "r"(a[1]), "r"(a[2]), "r"(a[3]), "r"(b0), "r"(b1));
}

__device__ __forceinline__ void ldmat4(uint32_t (&r)[4], uint32_t addr) {
    asm volatile("ldmatrix.sync.aligned.m8n8.x4.shared.b16 {%0,%1,%2,%3}, [%4];"
                 : "=r"(r[0]), "=r"(r[1]), "=r"(r[2]), "=r"(r[3]) : "r"(addr));
}

// block tile 128x128, warp tile 64x32; 3-pass bf16 split
__device__ __forceinline__ void mm_split(uint32_t sbase, int warp, int lane,
                                         float (&acc)[4][4][4]) {
    int warpm = warp & 1, warpn = warp >> 1;
    uint32_t a_off = (uint32_t)((warpm * 64 + (lane & 15)) * RSTRIDE + ((lane >> 4) << 4));
    uint32_t b_off = (uint32_t)((warpn * 32 + (lane & 7) + ((lane >> 4) << 3)) * RSTRIDE
                                + (((lane >> 3) & 1) << 4));
    uint32_t aHi = sbase + SM_AHI + a_off, aLo = sbase + SM_ALO + a_off;
    uint32_t bHi = sbase + SM_BHI + b_off, bLo = sbase + SM_BLO + b_off;

#pragma unroll
    for (int mt = 0; mt < 4; ++mt)
#pragma unroll
        for (int nt = 0; nt < 4; ++nt)
#pragma unroll
            for (int j = 0; j < 4; ++j) acc[mt][nt][j] = 0.f;

#pragma unroll
    for (int k0 = 0; k0 < 8; ++k0) {
        uint32_t ko = k0 * 32;
        uint32_t ahi[4][4], alo[4][4], bhi[2][4], blo[2][4];
#pragma unroll
        for (int mt = 0; mt < 4; ++mt) {
            ldmat4(ahi[mt], aHi + mt * 16 * RSTRIDE + ko);
            ldmat4(alo[mt], aLo + mt * 16 * RSTRIDE + ko);
        }
#pragma unroll
        for (int g = 0; g < 2; ++g) {
            ldmat4(bhi[g], bHi + g * 16 * RSTRIDE + ko);
            ldmat4(blo[g], bLo + g * 16 * RSTRIDE + ko);
        }
#pragma unroll
        for (int mt = 0; mt < 4; ++mt)
#pragma unroll
            for (int nt = 0; nt < 4; ++nt)
                mma16816(acc[mt][nt], ahi[mt], bhi[nt >> 1][(nt & 1) * 2], bhi[nt >> 1][(nt & 1) * 2 + 1]);
#pragma unroll
        for (int mt = 0; mt < 4; ++mt)
#pragma unroll
            for (int nt = 0; nt < 4; ++nt)
                mma16816(acc[mt][nt], ahi[mt], blo[nt >> 1][(nt & 1) * 2], blo[nt >> 1][(nt & 1) * 2 + 1]);
#pragma unroll
        for (int mt = 0; mt < 4; ++mt)
#pragma unroll
            for (int nt = 0; nt < 4; ++nt)
                mma16816(acc[mt][nt], alo[mt], bhi[nt >> 1][(nt & 1) * 2], bhi[nt >> 1][(nt & 1) * 2 + 1]);
    }
}

__device__ __forceinline__ void dump_acc(char* smc, int warp, int lane,
                                         const float (&acc)[4][4][4]) {
    int warpm = warp & 1, warpn = warp >> 1;
    int q = lane >> 2, tid = lane & 3;
    float* fb = (float*)(smc + SM_FB);
#pragma unroll
    for (int mt = 0; mt < 4; ++mt) {
        int r = warpm * 64 + mt * 16 + q;
#pragma unroll
        for (int nt = 0; nt < 4; ++nt) {
            int c = warpn * 32 + nt * 8 + 2 * tid;
            *(float2*)&fb[r * FB_STRIDE + c]       = make_float2(acc[mt][nt][0], acc[mt][nt][1]);
            *(float2*)&fb[(r + 8) * FB_STRIDE + c] = make_float2(acc[mt][nt][2], acc[mt][nt][3]);
        }
    }
}

// ---------------- node GEMMs ---------------------------------------------------
__global__ void __launch_bounds__(256)
k_node_mma(const float* __restrict__ nfeats, const float* __restrict__ b_node) {
    extern __shared__ char smc[];
    uint32_t sbase = smem_u32(smc);
    int t = threadIdx.x, warp = t >> 5, lane = t & 31;
    int m = blockIdx.y;
    int mat = (m == 0) ? 0 : (m == 1 ? 2 : 3);
    float* OUT = (m == 0) ? g_tsrc : (m == 1 ? g_tdst : g_hnode);

    const uint4* bh = (const uint4*)(g_Bhi + mat * 128 * 136);
    const uint4* bl = (const uint4*)(g_Blo + mat * 128 * 136);
    for (int i = t; i < 2176; i += 256) {
        ((uint4*)(smc + SM_BHI))[i] = bh[i];
        ((uint4*)(smc + SM_BLO))[i] = bl[i];
    }
    float* bias_s = (float*)(smc + SM_BIAS);
    for (int i = t; i < 128; i += 256) bias_s[i] = (m == 2) ? __ldg(&b_node[i]) : 0.f;

    const int ntiles = (NN + 127) / 128;   // 391
    int tile = blockIdx.x;
    float4 pf[16];
    if (tile < ntiles) prefetch_tile(pf, nfeats, tile * 128, NN, t);

    int prev_n0 = -1;
    for (; tile < ntiles; tile += gridDim.x) {
        int n0 = tile * 128;
        sts_tile(smc, pf, t);
        // prev-tile epilogue (overlaps STS issue)
        if (prev_n0 >= 0) {
            int n = prev_n0 + (t >> 1);
            if (n < NN) {
                int c0 = (t & 1) * 64;
                const float* frow = (float*)(smc + SM_FB) + (t >> 1) * FB_STRIDE + c0;
                float* op = OUT + (size_t)n * 128 + c0;
#pragma unroll
                for (int j = 0; j < 16; ++j) {
                    float4 v = *(const float4*)(frow + j * 4);
                    v.x += bias_s[c0 + j * 4];
                    v.y += bias_s[c0 + j * 4 + 1];
                    v.z += bias_s[c0 + j * 4 + 2];
                    v.w += bias_s[c0 + j * 4 + 3];
                    ((float4*)op)[j] = v;
                }
            }
        }
        __syncthreads();
        int nxt = tile + gridDim.x;
        if (nxt < ntiles) prefetch_tile(pf, nfeats, nxt * 128, NN, t);
        float acc[4][4][4];
        mm_split(sbase, warp, lane, acc);
        dump_acc(smc, warp, lane, acc);
        __syncthreads();
        prev_n0 = n0;
    }
    if (prev_n0 >= 0) {
        int n = prev_n0 + (t >> 1);
        if (n < NN) {
            int c0 = (t & 1) * 64;
            const float* frow = (float*)(smc + SM_FB) + (t >> 1) * FB_STRIDE + c0;
            float* op = OUT + (size_t)n * 128 + c0;
#pragma unroll
            for (int j = 0; j < 16; ++j) {
                float4 v = *(const float4*)(frow + j * 4);
                v.x += bias_s[c0 + j * 4];
                v.y += bias_s[c0 + j * 4 + 1];
                v.z += bias_s[c0 + j * 4 + 2];
                v.w += bias_s[c0 + j * 4 + 3];
                ((float4*)op)[j] = v;
            }
        }
    }
}

// ---------------- fused edge kernel ---------------------------------------------
__device__ __forceinline__ void edge_epilogue(char* smc, int e0, int t,
                                              const int* __restrict__ src,
                                              const int* __restrict__ dst,
                                              const float* __restrict__ norm,
                                              float* __restrict__ out2) {
    const float* bias_s = (const float*)(smc + SM_BIAS);
    const float* ws_s   = (const float*)(smc + SM_WS);
    int e = e0 + (t >> 1);
    int half = t & 1;
    int c0 = half * 64, h0 = half * 4;
    int s  = __ldg(&src[e]);
    int dd = __ldg(&dst[e]);
    float nrm = __ldg(&norm[e]);
    const float* frow = (const float*)(smc + SM_FB) + (t >> 1) * FB_STRIDE + c0;
    const float4* tsp = (const float4*)(g_tsrc + (size_t)s * 128 + c0);
    const float4* tdp = (const float4*)(g_tdst + (size_t)dd * 128 + c0);

    float pd[16];
#pragma unroll
    for (int d = 0; d < 16; ++d) pd[d] = 0.f;
    float ex[4], exn[4];
#pragma unroll
    for (int hl = 0; hl < 4; ++hl) {
        float lgv = 0.f;
#pragma unroll
        for (int j = 0; j < 4; ++j) {
            float4 dv = *(const float4*)(frow + hl * 16 + j * 4);
            float4 a4 = __ldg(tsp + hl * 4 + j);
            float4 b4 = __ldg(tdp + hl * 4 + j);
            int cb = c0 + hl * 16 + j * 4;
            float v0 = dv.x + a4.x + b4.x;
            float v1 = dv.y + a4.y + b4.y;
            float v2 = dv.z + a4.z + b4.z;
            float v3 = dv.w + a4.w + b4.w;
            v0 = (v0 > 0.f) ? v0 : 0.01f * v0;
            v1 = (v1 > 0.f) ? v1 : 0.01f * v1;
            v2 = (v2 > 0.f) ? v2 : 0.01f * v2;
            v3 = (v3 > 0.f) ? v3 : 0.01f * v3;
            v0 += bias_s[cb];
            v1 += bias_s[cb + 1];
            v2 += bias_s[cb + 2];
            v3 += bias_s[cb + 3];
            pd[j * 4]     += v0;
            pd[j * 4 + 1] += v1;
            pd[j * 4 + 2] += v2;
            pd[j * 4 + 3] += v3;
            lgv += v0 * ws_s[j * 4] + v1 * ws_s[j * 4 + 1]
                 + v2 * ws_s[j * 4 + 2] + v3 * ws_s[j * 4 + 3];
        }
        ex[hl]  = __expf(lgv);
        exn[hl] = ex[hl] * nrm;
    }
#pragma unroll
    for (int d = 0; d < 16; ++d) pd[d] += __shfl_xor_sync(0xffffffffu, pd[d], 1);
    if (!half) {
#pragma unroll
        for (int qj = 0; qj < 4; ++qj)
            ((float4*)(out2 + (size_t)e * DEF))[qj] =
                make_float4(pd[qj * 4], pd[qj * 4 + 1], pd[qj * 4 + 2], pd[qj * 4 + 3]);
    }
    ((float4*)g_a)[(size_t)e * 2 + half] = make_float4(exn[0], exn[1], exn[2], exn[3]);
#pragma unroll
    for (int hl = 0; hl < 4; ++hl)
        atomicAdd(&g_den[(size_t)dd * NHEAD + h0 + hl], ex[hl]);
}

__global__ void __launch_bounds__(256)
k_edge_mma(const float* __restrict__ efeats, const int* __restrict__ src,
           const int* __restrict__ dst, const float* __restrict__ norm,
           const float* __restrict__ bias, float* __restrict__ out2) {
    extern __shared__ char smc[];
    uint32_t sbase = smem_u32(smc);
    int t = threadIdx.x, warp = t >> 5, lane = t & 31;

    const uint4* bh = (const uint4*)(g_Bhi + 1 * 128 * 136);
    const uint4* bl = (const uint4*)(g_Blo + 1 * 128 * 136);
    for (int i = t; i < 2176; i += 256) {
        ((uint4*)(smc + SM_BHI))[i] = bh[i];
        ((uint4*)(smc + SM_BLO))[i] = bl[i];
    }
    float* bias_s = (float*)(smc + SM_BIAS);
    float* ws_s   = (float*)(smc + SM_WS);
    for (int i = t; i < 128; i += 256) bias_s[i] = __ldg(&bias[i]);
    if (t < DEF) ws_s[t] = g_wsum[t];

    const int ntiles = EE / 128;   // 3125 exact
    int tile = blockIdx.x;
    float4 pf[16];
    if (tile < ntiles) prefetch_tile(pf, efeats, tile * 128, 0x7fffffff, t);

    int prev_e0 = -1;
    for (; tile < ntiles; tile += gridDim.x) {
        int e0 = tile * 128;
        sts_tile(smc, pf, t);
        if (prev_e0 >= 0) edge_epilogue(smc, prev_e0, t, src, dst, norm, out2);
        __syncthreads();
        int nxt = tile + gridDim.x;
        if (nxt < ntiles) prefetch_tile(pf, efeats, nxt * 128, 0x7fffffff, t);
        float acc[4][4][4];
        mm_split(sbase, warp, lane, acc);
        dump_acc(smc, warp, lane, acc);
        __syncthreads();
        prev_e0 = e0;
    }
    if (prev_e0 >= 0) edge_epilogue(smc, prev_e0, t, src, dst, norm, out2);
}

// ---------------- message passing ------------------------------------------------
__global__ void k_msg(const int* __restrict__ src, const int* __restrict__ dst,
                      float* __restrict__ out1) {
    int gid = blockIdx.x * blockDim.x + threadIdx.x;
    int e = gid >> 4, d = gid & 15;
    if (e >= EE) return;
    int s  = __ldg(&src[e]);
    int dd = __ldg(&dst[e]);
    float acc = 0.f;
#pragma unroll
    for (int h = 0; h < NHEAD; ++h) {
        float w = __fdividef(g_a[(size_t)e * NHEAD + h],
                             g_den[(size_t)dd * NHEAD + h]);
        acc += w * g_hnode[(size_t)s * 128 + h * DNF + d];
    }
    atomicAdd(&out1[(size_t)dd * DNF + d], acc);
}

// ---------------- launch ----------------------------------------------------------
extern "C" void kernel_launch(void* const* d_in, const int* in_sizes, int n_in,
                              void* d_out, int out_size) {
    const float* nfeats  = (const float*)d_in[0];
    const float* efeats  = (const float*)d_in[1];
    const float* norm    = (const float*)d_in[2];
    const int*   src     = (const int*)d_in[3];
    const int*   dst     = (const int*)d_in[4];
    const float* W_ni    = (const float*)d_in[5];
    const float* W_nj    = (const float*)d_in[6];
    const float* W_fij   = (const float*)d_in[7];
    const float* W_edges = (const float*)d_in[8];
    const float* W_attn  = (const float*)d_in[9];
    const float* bias    = (const float*)d_in[10];
    const float* W_node  = (const float*)d_in[11];
    const float* b_node  = (const float*)d_in[12];

    float* out1 = (float*)d_out;
    float* out2 = out1 + (size_t)NN * DNF;

    cudaFuncSetAttribute(k_node_mma, cudaFuncAttributeMaxDynamicSharedMemorySize, SM_TOTAL);
    cudaFuncSetAttribute(k_edge_mma, cudaFuncAttributeMaxDynamicSharedMemorySize, SM_TOTAL);

    k_init<<<3125, 256>>>(out1);
    k_weights<<<dim3(128, 4), 128>>>(W_edges, W_ni, W_nj, W_fij, W_node, W_attn);
    k_wconv<<<256, 256>>>();
    k_node_mma<<<dim3(148, 3), 256, SM_TOTAL>>>(nfeats, b_node);
    k_edge_mma<<<148, 256, SM_TOTAL>>>(efeats, src, dst, norm, bias, out2);
    k_msg<<<(EE * DNF + 255) / 256, 256>>>(src, dst, out1);
}

// round 7
// speedup vs baseline: 1.4254x; 1.4254x over previous
#include <cuda_runtime.h>
#include <cuda_fp16.h>
#include <cstring>
#include <cstdint>

#define NN 50000
#define EE 400000
#define NHEAD 8
#define DEF 16
#define DNF 16

// ---------------- device global scratch ------------------------------------
__device__ float g_N1t[128 * 128];   // (W1@W_ni)^T: [k][c]
__device__ float g_A2t[128 * 128];   // (W2@W_fij)^T
__device__ float g_N3t[128 * 128];   // (W3@W_nj)^T
__device__ float g_Wnt[128 * 128];   // W_node^T
__device__ float g_wsum[DEF];
// B operand as fp16 [n][k], row stride 136 elements (hi only — 2-pass split)
__device__ __half g_Bh[4 * 128 * 136];
__device__ float g_tsrc[NN * 128];
__device__ float g_tdst[NN * 128];
__device__ float g_hnode[NN * 128];
__device__ float g_a[EE * NHEAD];    // exp(logit) * norm
__device__ float g_den[NN * NHEAD];  // sum of raw exp(logit)

// ---------------- smem layout (bytes) ---------------------------------------
#define RSTRIDE 272                 // 136 fp16 per row
#define AB_BYTES (128 * RSTRIDE)    // 34816
#define SM_BIAS 0
#define SM_WS   512
#define SM_A    1024
#define SM_AHI  SM_A
#define SM_ALO  (SM_A + AB_BYTES)       // 35840
#define SM_BHI  (SM_ALO + AB_BYTES)     // 70656
#define SM_TOTAL (SM_BHI + AB_BYTES)    // 105472
#define SM_FBUF SM_A                    // fp32 staging overlays A hi+lo (67584 <= 69632)
#define FB_STRIDE 132

// ---------------- small kernels ----------------------------------------------
__global__ void k_init(float* __restrict__ out1) {
    int i = blockIdx.x * blockDim.x + threadIdx.x;
    if (i < NN * NHEAD) g_den[i] = 0.f;
    if (i < NN * DNF)   out1[i] = 0.f;
}

__global__ void k_weights(const float* __restrict__ W_edges,
                          const float* __restrict__ W_ni,
                          const float* __restrict__ W_nj,
                          const float* __restrict__ W_fij,
                          const float* __restrict__ W_node,
                          const float* __restrict__ W_attn) {
    int k = blockIdx.x, c = threadIdx.x, m = blockIdx.y;
    if (m == 0) {
        float acc = 0.f;
        for (int j = 0; j < 128; ++j) acc += W_edges[c * 384 + j] * W_ni[j * 128 + k];
        g_N1t[k * 128 + c] = acc;
    } else if (m == 1) {
        float acc = 0.f;
        for (int j = 0; j < 128; ++j) acc += W_edges[c * 384 + 128 + j] * W_fij[j * 128 + k];
        g_A2t[k * 128 + c] = acc;
    } else if (m == 2) {
        float acc = 0.f;
        for (int j = 0; j < 128; ++j) acc += W_edges[c * 384 + 256 + j] * W_nj[j * 128 + k];
        g_N3t[k * 128 + c] = acc;
    } else {
        g_Wnt[k * 128 + c] = W_node[c * 128 + k];
        if (k == 0 && c < DEF) {
            float s = 0.f;
            for (int h = 0; h < NHEAD; ++h) s += W_attn[h * DEF + c];
            g_wsum[c] = s;
        }
    }
}

// convert combined weights into fp16 [n][k] stride-136 operand
__global__ void k_wconv() {
    int idx = blockIdx.x * blockDim.x + threadIdx.x;  // 65536
    int m = idx >> 14, r = idx & 16383;
    int n = r >> 7, k = r & 127;                      // B[n][k] = Wt[k][n]
    const float* srcs[4] = {g_N1t, g_A2t, g_N3t, g_Wnt};
    g_Bh[m * 128 * 136 + n * 136 + k] = __float2half_rn(srcs[m][k * 128 + n]);
}

// ---------------- fp32 -> fp16 hi/lo tile stage -------------------------------
__device__ __forceinline__ void split8(const float4 v0, const float4 v1, uint4& H, uint4& L) {
    float x[8] = {v0.x, v0.y, v0.z, v0.w, v1.x, v1.y, v1.z, v1.w};
    unsigned hu[4], lu[4];
#pragma unroll
    for (int j = 0; j < 4; ++j) {
        __half2 hp = __floats2half2_rn(x[2 * j], x[2 * j + 1]);
        float ra = x[2 * j]     - __low2float(hp);
        float rb = x[2 * j + 1] - __high2float(hp);
        __half2 lp = __floats2half2_rn(ra, rb);
        memcpy(&hu[j], &hp, 4);
        memcpy(&lu[j], &lp, 4);
    }
    H = make_uint4(hu[0], hu[1], hu[2], hu[3]);
    L = make_uint4(lu[0], lu[1], lu[2], lu[3]);
}

// stage 128 x 128 fp32 rows into fp16 hi/lo smem
__device__ __forceinline__ void load_tile(char* smc, const float* __restrict__ srcp,
                                          int base, int limit, int t) {
    for (int i = t; i < 2048; i += 256) {
        int row = i >> 4, col = (i & 15) * 8;
        int gr = base + row;
        float4 v0, v1;
        if (gr < limit) {
            v0 = __ldg((const float4*)(srcp + (size_t)gr * 128 + col));
            v1 = __ldg((const float4*)(srcp + (size_t)gr * 128 + col + 4));
        } else {
            v0 = make_float4(0.f, 0.f, 0.f, 0.f); v1 = v0;
        }
        uint4 H, L;
        split8(v0, v1, H, L);
        *(uint4*)(smc + SM_AHI + row * RSTRIDE + col * 2) = H;
        *(uint4*)(smc + SM_ALO + row * RSTRIDE + col * 2) = L;
    }
}

// ---------------- mma.sync fp16 2-pass GEMM core ------------------------------
__device__ __forceinline__ void mma16816(float (&d)[4], const uint32_t (&a)[4],
                                         const uint32_t (&b)[2]) {
    asm("mma.sync.aligned.m16n8k16.row.col.f32.f16.f16.f32 "
        "{%0,%1,%2,%3}, {%4,%5,%6,%7}, {%8,%9}, {%0,%1,%2,%3};"
        : "+f"(d[0]), "+f"(d[1]), "+f"(d[2]), "+f"(d[3])
        : "r"(a[0]), "r"(a[1]), "r"(a[2]), "r"(a[3]), "r"(b[0]), "r"(b[1]));
}

__device__ __forceinline__ uint32_t lds32(const char* base, int r, int k) {
    return *(const uint32_t*)(base + r * RSTRIDE + k * 2);
}

// block tile 128x128, warp tile 64x32; D = (Ahi + Alo) * Bhi
__device__ __forceinline__ void mm_split(char* smc, int warp, int lane,
                                         float (&acc)[4][4][4]) {
    int warpm = warp & 1, warpn = warp >> 1;
    int q = lane >> 2, tid = lane & 3;
    const char* Ahi = smc + SM_AHI;
    const char* Alo = smc + SM_ALO;
    const char* Bhi = smc + SM_BHI;

#pragma unroll
    for (int mt = 0; mt < 4; ++mt)
#pragma unroll
        for (int nt = 0; nt < 4; ++nt)
#pragma unroll
            for (int j = 0; j < 4; ++j) acc[mt][nt][j] = 0.f;

#pragma unroll
    for (int k0 = 0; k0 < 8; ++k0) {
        int kk = k0 * 16 + 2 * tid;
        uint32_t ahi[4][4], alo[4][4], bhi[4][2];
#pragma unroll
        for (int mt = 0; mt < 4; ++mt) {
            int r = warpm * 64 + mt * 16 + q;
            ahi[mt][0] = lds32(Ahi, r, kk);
            ahi[mt][1] = lds32(Ahi, r + 8, kk);
            ahi[mt][2] = lds32(Ahi, r, kk + 8);
            ahi[mt][3] = lds32(Ahi, r + 8, kk + 8);
            alo[mt][0] = lds32(Alo, r, kk);
            alo[mt][1] = lds32(Alo, r + 8, kk);
            alo[mt][2] = lds32(Alo, r, kk + 8);
            alo[mt][3] = lds32(Alo, r + 8, kk + 8);
        }
#pragma unroll
        for (int nt = 0; nt < 4; ++nt) {
            int n = warpn * 32 + nt * 8 + q;
            bhi[nt][0] = lds32(Bhi, n, kk);
            bhi[nt][1] = lds32(Bhi, n, kk + 8);
        }
#pragma unroll
        for (int mt = 0; mt < 4; ++mt)
#pragma unroll
            for (int nt = 0; nt < 4; ++nt) mma16816(acc[mt][nt], ahi[mt], bhi[nt]);
#pragma unroll
        for (int mt = 0; mt < 4; ++mt)
#pragma unroll
            for (int nt = 0; nt < 4; ++nt) mma16816(acc[mt][nt], alo[mt], bhi[nt]);
    }
}

__device__ __forceinline__ void dump_acc(char* smc, int warp, int lane,
                                         const float (&acc)[4][4][4]) {
    int warpm = warp & 1, warpn = warp >> 1;
    int q = lane >> 2, tid = lane & 3;
    float* fb = (float*)(smc + SM_FBUF);
#pragma unroll
    for (int mt = 0; mt < 4; ++mt) {
        int r = warpm * 64 + mt * 16 + q;
#pragma unroll
        for (int nt = 0; nt < 4; ++nt) {
            int c = warpn * 32 + nt * 8 + 2 * tid;
            *(float2*)&fb[r * FB_STRIDE + c]       = make_float2(acc[mt][nt][0], acc[mt][nt][1]);
            *(float2*)&fb[(r + 8) * FB_STRIDE + c] = make_float2(acc[mt][nt][2], acc[mt][nt][3]);
        }
    }
}

// ---------------- node GEMMs -------------------------------------------------
__global__ void __launch_bounds__(256, 1)
k_node_mma(const float* __restrict__ nfeats, const float* __restrict__ b_node) {
    extern __shared__ char smc[];
    int t = threadIdx.x, warp = t >> 5, lane = t & 31;
    int m = blockIdx.y;
    int mat = (m == 0) ? 0 : (m == 1 ? 2 : 3);
    float* OUT = (m == 0) ? g_tsrc : (m == 1 ? g_tdst : g_hnode);

    const uint4* bh = (const uint4*)(g_Bh + mat * 128 * 136);
    for (int i = t; i < 2176; i += 256)
        ((uint4*)(smc + SM_BHI))[i] = bh[i];
    float* bias_s = (float*)(smc + SM_BIAS);
    for (int i = t; i < 128; i += 256) bias_s[i] = (m == 2) ? __ldg(&b_node[i]) : 0.f;

    int ntiles = (NN + 127) / 128;   // 391
    for (int tile = blockIdx.x; tile < ntiles; tile += gridDim.x) {
        int n0 = tile * 128;
        load_tile(smc, nfeats, n0, NN, t);
        __syncthreads();
        float acc[4][4][4];
        mm_split(smc, warp, lane, acc);
        __syncthreads();        // all LDS reads of A done before fbuf overlay
        dump_acc(smc, warp, lane, acc);
        __syncthreads();
        // epilogue: 2 threads per row, 64 cols each
        int n = n0 + (t >> 1);
        if (n < NN) {
            int c0 = (t & 1) * 64;
            const float* frow = (float*)(smc + SM_FBUF) + (t >> 1) * FB_STRIDE + c0;
            float* op = OUT + (size_t)n * 128 + c0;
#pragma unroll
            for (int j = 0; j < 16; ++j) {
                float4 v = *(const float4*)(frow + j * 4);
                v.x += bias_s[c0 + j * 4];
                v.y += bias_s[c0 + j * 4 + 1];
                v.z += bias_s[c0 + j * 4 + 2];
                v.w += bias_s[c0 + j * 4 + 3];
                ((float4*)op)[j] = v;
            }
        }
        __syncthreads();        // epilogue reads done before next load_tile
    }
}

// ---------------- fused edge kernel ------------------------------------------
__global__ void __launch_bounds__(256, 1)
k_edge_mma(const float* __restrict__ efeats, const int* __restrict__ src,
           const int* __restrict__ dst, const float* __restrict__ norm,
           const float* __restrict__ bias, float* __restrict__ out2) {
    extern __shared__ char smc[];
    int t = threadIdx.x, warp = t >> 5, lane = t & 31;

    const uint4* bh = (const uint4*)(g_Bh + 1 * 128 * 136);
    for (int i = t; i < 2176; i += 256)
        ((uint4*)(smc + SM_BHI))[i] = bh[i];
    float* bias_s = (float*)(smc + SM_BIAS);
    float* ws_s   = (float*)(smc + SM_WS);
    for (int i = t; i < 128; i += 256) bias_s[i] = __ldg(&bias[i]);
    if (t < DEF) ws_s[t] = g_wsum[t];

    const int ntiles = EE / 128;   // 3125 exact
    for (int tile = blockIdx.x; tile < ntiles; tile += gridDim.x) {
        int e0 = tile * 128;
        load_tile(smc, efeats, e0, 0x7fffffff, t);
        __syncthreads();
        float acc[4][4][4];
        mm_split(smc, warp, lane, acc);
        __syncthreads();
        dump_acc(smc, warp, lane, acc);
        __syncthreads();

        // epilogue: 2 threads per edge row (halves of 128 cols = 4 heads each)
        int e = e0 + (t >> 1);
        int half = t & 1;
        int c0 = half * 64, h0 = half * 4;
        int s  = __ldg(&src[e]);
        int dd = __ldg(&dst[e]);
        float nrm = __ldg(&norm[e]);
        const float* frow = (float*)(smc + SM_FBUF) + (t >> 1) * FB_STRIDE + c0;
        const float4* tsp = (const float4*)(g_tsrc + (size_t)s * 128 + c0);
        const float4* tdp = (const float4*)(g_tdst + (size_t)dd * 128 + c0);

        float pd[16];
#pragma unroll
        for (int d = 0; d < 16; ++d) pd[d] = 0.f;
        float ex[4], exn[4];
#pragma unroll
        for (int hl = 0; hl < 4; ++hl) {
            float lgv = 0.f;
#pragma unroll
            for (int j = 0; j < 4; ++j) {
                float4 dv = *(const float4*)(frow + hl * 16 + j * 4);
                float4 a4 = __ldg(tsp + hl * 4 + j);
                float4 b4 = __ldg(tdp + hl * 4 + j);
                int cb = c0 + hl * 16 + j * 4;
                float v0 = dv.x + a4.x + b4.x;
                float v1 = dv.y + a4.y + b4.y;
                float v2 = dv.z + a4.z + b4.z;
                float v3 = dv.w + a4.w + b4.w;
                v0 = (v0 > 0.f) ? v0 : 0.01f * v0;
                v1 = (v1 > 0.f) ? v1 : 0.01f * v1;
                v2 = (v2 > 0.f) ? v2 : 0.01f * v2;
                v3 = (v3 > 0.f) ? v3 : 0.01f * v3;
                v0 += bias_s[cb];
                v1 += bias_s[cb + 1];
                v2 += bias_s[cb + 2];
                v3 += bias_s[cb + 3];
                pd[j * 4]     += v0;
                pd[j * 4 + 1] += v1;
                pd[j * 4 + 2] += v2;
                pd[j * 4 + 3] += v3;
                lgv += v0 * ws_s[j * 4] + v1 * ws_s[j * 4 + 1]
                     + v2 * ws_s[j * 4 + 2] + v3 * ws_s[j * 4 + 3];
            }
            ex[hl]  = __expf(lgv);
            exn[hl] = ex[hl] * nrm;
        }
        // combine head-sum partials across the thread pair
#pragma unroll
        for (int d = 0; d < 16; ++d) pd[d] += __shfl_xor_sync(0xffffffffu, pd[d], 1);
        if (!half) {
#pragma unroll
            for (int qj = 0; qj < 4; ++qj)
                ((float4*)(out2 + (size_t)e * DEF))[qj] =
                    make_float4(pd[qj * 4], pd[qj * 4 + 1], pd[qj * 4 + 2], pd[qj * 4 + 3]);
        }
        ((float4*)g_a)[(size_t)e * 2 + half] = make_float4(exn[0], exn[1], exn[2], exn[3]);
#pragma unroll
        for (int hl = 0; hl < 4; ++hl)
            atomicAdd(&g_den[(size_t)dd * NHEAD + h0 + hl], ex[hl]);
        __syncthreads();
    }
}

// ---------------- message passing --------------------------------------------
__global__ void k_msg(const int* __restrict__ src, const int* __restrict__ dst,
                      float* __restrict__ out1) {
    int gid = blockIdx.x * blockDim.x + threadIdx.x;
    int e = gid >> 4, d = gid & 15;
    if (e >= EE) return;
    int s  = __ldg(&src[e]);
    int dd = __ldg(&dst[e]);
    float acc = 0.f;
#pragma unroll
    for (int h = 0; h < NHEAD; ++h) {
        float w = __fdividef(g_a[(size_t)e * NHEAD + h],
                             g_den[(size_t)dd * NHEAD + h]);
        acc += w * g_hnode[(size_t)s * 128 + h * DNF + d];
    }
    atomicAdd(&out1[(size_t)dd * DNF + d], acc);
}

// ---------------- launch ------------------------------------------------------
extern "C" void kernel_launch(void* const* d_in, const int* in_sizes, int n_in,
                              void* d_out, int out_size) {
    const float* nfeats  = (const float*)d_in[0];
    const float* efeats  = (const float*)d_in[1];
    const float* norm    = (const float*)d_in[2];
    const int*   src     = (const int*)d_in[3];
    const int*   dst     = (const int*)d_in[4];
    const float* W_ni    = (const float*)d_in[5];
    const float* W_nj    = (const float*)d_in[6];
    const float* W_fij   = (const float*)d_in[7];
    const float* W_edges = (const float*)d_in[8];
    const float* W_attn  = (const float*)d_in[9];
    const float* bias    = (const float*)d_in[10];
    const float* W_node  = (const float*)d_in[11];
    const float* b_node  = (const float*)d_in[12];

    float* out1 = (float*)d_out;
    float* out2 = out1 + (size_t)NN * DNF;

    cudaFuncSetAttribute(k_node_mma, cudaFuncAttributeMaxDynamicSharedMemorySize, SM_TOTAL);
    cudaFuncSetAttribute(k_edge_mma, cudaFuncAttributeMaxDynamicSharedMemorySize, SM_TOTAL);

    k_init<<<3125, 256>>>(out1);
    k_weights<<<dim3(128, 4), 128>>>(W_edges, W_ni, W_nj, W_fij, W_node, W_attn);
    k_wconv<<<256, 256>>>();
    k_node_mma<<<dim3(148, 3), 256, SM_TOTAL>>>(nfeats, b_node);
    k_edge_mma<<<148, 256, SM_TOTAL>>>(efeats, src, dst, norm, bias, out2);
    k_msg<<<(EE * DNF + 255) / 256, 256>>>(src, dst, out1);
}

// round 8
// speedup vs baseline: 1.6161x; 1.1338x over previous
#include <cuda_runtime.h>
#include <cuda_fp16.h>
#include <cstring>
#include <cstdint>

#define NN 50000
#define EE 400000
#define NHEAD 8
#define DEF 16
#define DNF 16

// ---------------- device global scratch ------------------------------------
__device__ float g_N1t[128 * 128];   // (W1@W_ni)^T: [k][c]
__device__ float g_A2t[128 * 128];   // (W2@W_fij)^T
__device__ float g_N3t[128 * 128];   // (W3@W_nj)^T
__device__ float g_Wnt[128 * 128];   // W_node^T
__device__ float g_wsum[DEF];
// B operand as fp16 [n][k], row stride 136 elements (hi only — 2-pass split)
__device__ __half g_Bh[4 * 128 * 136];
__device__ __half g_tsrc[NN * 128];  // fp16 projected node tables
__device__ __half g_tdst[NN * 128];
__device__ __half g_hnode[NN * 128];
__device__ float g_a[EE * NHEAD];    // exp(logit) * norm
__device__ float g_den[NN * NHEAD];  // sum of raw exp(logit)

// ---------------- smem layouts (bytes) ---------------------------------------
#define RSTRIDE 272                 // 136 fp16 per row
#define AB_BYTES (128 * RSTRIDE)    // 34816

// edge kernel layout (as round 7)
#define SM_BIAS 0
#define SM_WS   512
#define SM_A    1024
#define SM_AHI  SM_A
#define SM_ALO  (SM_A + AB_BYTES)       // 35840
#define SM_BHI  (SM_ALO + AB_BYTES)     // 70656
#define SM_TOTAL (SM_BHI + AB_BYTES)    // 105472
#define SM_FBUF SM_A                    // fp32 staging overlays A hi+lo
#define FB_STRIDE 132

// fused node kernel layout
#define SMN_BIAS 0
#define SMN_AHI  1024
#define SMN_ALO  (SMN_AHI + AB_BYTES)
#define SMN_B0   (SMN_ALO + AB_BYTES)           // 70656
#define SMN_TOTAL (SMN_B0 + 3 * AB_BYTES)       // 175104

// ---------------- small kernels ----------------------------------------------
__global__ void k_init(float* __restrict__ out1) {
    int i = blockIdx.x * blockDim.x + threadIdx.x;
    if (i < NN * NHEAD) g_den[i] = 0.f;
    if (i < NN * DNF)   out1[i] = 0.f;
}

__global__ void k_weights(const float* __restrict__ W_edges,
                          const float* __restrict__ W_ni,
                          const float* __restrict__ W_nj,
                          const float* __restrict__ W_fij,
                          const float* __restrict__ W_node,
                          const float* __restrict__ W_attn) {
    int k = blockIdx.x, c = threadIdx.x, m = blockIdx.y;
    if (m == 0) {
        float acc = 0.f;
        for (int j = 0; j < 128; ++j) acc += W_edges[c * 384 + j] * W_ni[j * 128 + k];
        g_N1t[k * 128 + c] = acc;
    } else if (m == 1) {
        float acc = 0.f;
        for (int j = 0; j < 128; ++j) acc += W_edges[c * 384 + 128 + j] * W_fij[j * 128 + k];
        g_A2t[k * 128 + c] = acc;
    } else if (m == 2) {
        float acc = 0.f;
        for (int j = 0; j < 128; ++j) acc += W_edges[c * 384 + 256 + j] * W_nj[j * 128 + k];
        g_N3t[k * 128 + c] = acc;
    } else {
        g_Wnt[k * 128 + c] = W_node[c * 128 + k];
        if (k == 0 && c < DEF) {
            float s = 0.f;
            for (int h = 0; h < NHEAD; ++h) s += W_attn[h * DEF + c];
            g_wsum[c] = s;
        }
    }
}

__global__ void k_wconv() {
    int idx = blockIdx.x * blockDim.x + threadIdx.x;  // 65536
    int m = idx >> 14, r = idx & 16383;
    int n = r >> 7, k = r & 127;                      // B[n][k] = Wt[k][n]
    const float* srcs[4] = {g_N1t, g_A2t, g_N3t, g_Wnt};
    g_Bh[m * 128 * 136 + n * 136 + k] = __float2half_rn(srcs[m][k * 128 + n]);
}

// ---------------- fp32 -> fp16 hi/lo tile stage -------------------------------
__device__ __forceinline__ void split8(const float4 v0, const float4 v1, uint4& H, uint4& L) {
    float x[8] = {v0.x, v0.y, v0.z, v0.w, v1.x, v1.y, v1.z, v1.w};
    unsigned hu[4], lu[4];
#pragma unroll
    for (int j = 0; j < 4; ++j) {
        __half2 hp = __floats2half2_rn(x[2 * j], x[2 * j + 1]);
        float ra = x[2 * j]     - __low2float(hp);
        float rb = x[2 * j + 1] - __high2float(hp);
        __half2 lp = __floats2half2_rn(ra, rb);
        memcpy(&hu[j], &hp, 4);
        memcpy(&lu[j], &lp, 4);
    }
    H = make_uint4(hu[0], hu[1], hu[2], hu[3]);
    L = make_uint4(lu[0], lu[1], lu[2], lu[3]);
}

__device__ __forceinline__ void load_tile(char* smc, int ahioff, int alooff,
                                          const float* __restrict__ srcp,
                                          int base, int limit, int t) {
    for (int i = t; i < 2048; i += 256) {
        int row = i >> 4, col = (i & 15) * 8;
        int gr = base + row;
        float4 v0, v1;
        if (gr < limit) {
            v0 = __ldg((const float4*)(srcp + (size_t)gr * 128 + col));
            v1 = __ldg((const float4*)(srcp + (size_t)gr * 128 + col + 4));
        } else {
            v0 = make_float4(0.f, 0.f, 0.f, 0.f); v1 = v0;
        }
        uint4 H, L;
        split8(v0, v1, H, L);
        *(uint4*)(smc + ahioff + row * RSTRIDE + col * 2) = H;
        *(uint4*)(smc + alooff + row * RSTRIDE + col * 2) = L;
    }
}

// ---------------- mma.sync fp16 2-pass GEMM core ------------------------------
__device__ __forceinline__ void mma16816(float (&d)[4], const uint32_t (&a)[4],
                                         const uint32_t (&b)[2]) {
    asm("mma.sync.aligned.m16n8k16.row.col.f32.f16.f16.f32 "
        "{%0,%1,%2,%3}, {%4,%5,%6,%7}, {%8,%9}, {%0,%1,%2,%3};"
        : "+f"(d[0]), "+f"(d[1]), "+f"(d[2]), "+f"(d[3])
        : "r"(a[0]), "r"(a[1]), "r"(a[2]), "r"(a[3]), "r"(b[0]), "r"(b[1]));
}

__device__ __forceinline__ uint32_t lds32(const char* base, int r, int k) {
    return *(const uint32_t*)(base + r * RSTRIDE + k * 2);
}

// block tile 128x128, warp tile 64x32; D = (Ahi + Alo) * Bhi
__device__ __forceinline__ void mm_split(const char* Ahi, const char* Alo,
                                         const char* Bhi, int warp, int lane,
                                         float (&acc)[4][4][4]) {
    int warpm = warp & 1, warpn = warp >> 1;
    int q = lane >> 2, tid = lane & 3;

#pragma unroll
    for (int mt = 0; mt < 4; ++mt)
#pragma unroll
        for (int nt = 0; nt < 4; ++nt)
#pragma unroll
            for (int j = 0; j < 4; ++j) acc[mt][nt][j] = 0.f;

#pragma unroll
    for (int k0 = 0; k0 < 8; ++k0) {
        int kk = k0 * 16 + 2 * tid;
        uint32_t ahi[4][4], alo[4][4], bhi[4][2];
#pragma unroll
        for (int mt = 0; mt < 4; ++mt) {
            int r = warpm * 64 + mt * 16 + q;
            ahi[mt][0] = lds32(Ahi, r, kk);
            ahi[mt][1] = lds32(Ahi, r + 8, kk);
            ahi[mt][2] = lds32(Ahi, r, kk + 8);
            ahi[mt][3] = lds32(Ahi, r + 8, kk + 8);
            alo[mt][0] = lds32(Alo, r, kk);
            alo[mt][1] = lds32(Alo, r + 8, kk);
            alo[mt][2] = lds32(Alo, r, kk + 8);
            alo[mt][3] = lds32(Alo, r + 8, kk + 8);
        }
#pragma unroll
        for (int nt = 0; nt < 4; ++nt) {
            int n = warpn * 32 + nt * 8 + q;
            bhi[nt][0] = lds32(Bhi, n, kk);
            bhi[nt][1] = lds32(Bhi, n, kk + 8);
        }
#pragma unroll
        for (int mt = 0; mt < 4; ++mt)
#pragma unroll
            for (int nt = 0; nt < 4; ++nt) mma16816(acc[mt][nt], ahi[mt], bhi[nt]);
#pragma unroll
        for (int mt = 0; mt < 4; ++mt)
#pragma unroll
            for (int nt = 0; nt < 4; ++nt) mma16816(acc[mt][nt], alo[mt], bhi[nt]);
    }
}

__device__ __forceinline__ void dump_acc(char* smc, int warp, int lane,
                                         const float (&acc)[4][4][4]) {
    int warpm = warp & 1, warpn = warp >> 1;
    int q = lane >> 2, tid = lane & 3;
    float* fb = (float*)(smc + SM_FBUF);
#pragma unroll
    for (int mt = 0; mt < 4; ++mt) {
        int r = warpm * 64 + mt * 16 + q;
#pragma unroll
        for (int nt = 0; nt < 4; ++nt) {
            int c = warpn * 32 + nt * 8 + 2 * tid;
            *(float2*)&fb[r * FB_STRIDE + c]       = make_float2(acc[mt][nt][0], acc[mt][nt][1]);
            *(float2*)&fb[(r + 8) * FB_STRIDE + c] = make_float2(acc[mt][nt][2], acc[mt][nt][3]);
        }
    }
}

// ---------------- fused node GEMMs: t_src / t_dst / h_node --------------------
__global__ void __launch_bounds__(256, 1)
k_node_mma(const float* __restrict__ nfeats, const float* __restrict__ b_node) {
    extern __shared__ char smc[];
    int t = threadIdx.x, warp = t >> 5, lane = t & 31;
    int warpm = warp & 1, warpn = warp >> 1;
    int q = lane >> 2, tid = lane & 3;

    // stage the 3 B operands (mats 0: tsrc, 2: tdst, 3: hnode)
    for (int i = t; i < 2176; i += 256) {
        ((uint4*)(smc + SMN_B0))[i]                = ((const uint4*)(g_Bh + 0 * 128 * 136))[i];
        ((uint4*)(smc + SMN_B0 + AB_BYTES))[i]     = ((const uint4*)(g_Bh + 2 * 128 * 136))[i];
        ((uint4*)(smc + SMN_B0 + 2 * AB_BYTES))[i] = ((const uint4*)(g_Bh + 3 * 128 * 136))[i];
    }
    float* bias_s = (float*)(smc + SMN_BIAS);
    for (int i = t; i < 128; i += 256) bias_s[i] = __ldg(&b_node[i]);

    const int ntiles = (NN + 127) / 128;   // 391
    for (int tile = blockIdx.x; tile < ntiles; tile += gridDim.x) {
        int n0 = tile * 128;
        load_tile(smc, SMN_AHI, SMN_ALO, nfeats, n0, NN, t);
        __syncthreads();
#pragma unroll 1
        for (int mat = 0; mat < 3; ++mat) {
            __half* OUT = (mat == 0) ? g_tsrc : (mat == 1 ? g_tdst : g_hnode);
            float acc[4][4][4];
            mm_split(smc + SMN_AHI, smc + SMN_ALO,
                     smc + SMN_B0 + mat * AB_BYTES, warp, lane, acc);
            // direct fragment -> fp16 gmem store
#pragma unroll
            for (int mt = 0; mt < 4; ++mt) {
                int rr = warpm * 64 + mt * 16 + q;
#pragma unroll
                for (int nt = 0; nt < 4; ++nt) {
                    int cc = warpn * 32 + nt * 8 + 2 * tid;
                    float b0 = 0.f, b1 = 0.f;
                    if (mat == 2) { b0 = bias_s[cc]; b1 = bias_s[cc + 1]; }
                    int n1 = n0 + rr, n2 = n1 + 8;
                    if (n1 < NN)
                        *(__half2*)(OUT + (size_t)n1 * 128 + cc) =
                            __floats2half2_rn(acc[mt][nt][0] + b0, acc[mt][nt][1] + b1);
                    if (n2 < NN)
                        *(__half2*)(OUT + (size_t)n2 * 128 + cc) =
                            __floats2half2_rn(acc[mt][nt][2] + b0, acc[mt][nt][3] + b1);
                }
            }
        }
        __syncthreads();   // all reads of A done before next load_tile
    }
}

// ---------------- fused edge kernel ------------------------------------------
__device__ __forceinline__ float2 h2f2(uint32_t u) {
    __half2 h;
    memcpy(&h, &u, 4);
    return __half22float2(h);
}

__global__ void __launch_bounds__(256, 1)
k_edge_mma(const float* __restrict__ efeats, const int* __restrict__ src,
           const int* __restrict__ dst, const float* __restrict__ norm,
           const float* __restrict__ bias, float* __restrict__ out2) {
    extern __shared__ char smc[];
    int t = threadIdx.x, warp = t >> 5, lane = t & 31;

    const uint4* bh = (const uint4*)(g_Bh + 1 * 128 * 136);
    for (int i = t; i < 2176; i += 256)
        ((uint4*)(smc + SM_BHI))[i] = bh[i];
    float* bias_s = (float*)(smc + SM_BIAS);
    float* ws_s   = (float*)(smc + SM_WS);
    for (int i = t; i < 128; i += 256) bias_s[i] = __ldg(&bias[i]);
    if (t < DEF) ws_s[t] = g_wsum[t];

    const int ntiles = EE / 128;   // 3125 exact
    for (int tile = blockIdx.x; tile < ntiles; tile += gridDim.x) {
        int e0 = tile * 128;
        load_tile(smc, SM_AHI, SM_ALO, efeats, e0, 0x7fffffff, t);
        __syncthreads();
        float acc[4][4][4];
        mm_split(smc + SM_AHI, smc + SM_ALO, smc + SM_BHI, warp, lane, acc);
        __syncthreads();
        dump_acc(smc, warp, lane, acc);
        __syncthreads();

        // epilogue: 2 threads per edge row (halves of 128 cols = 4 heads each)
        int e = e0 + (t >> 1);
        int half = t & 1;
        int c0 = half * 64, h0 = half * 4;
        int s  = __ldg(&src[e]);
        int dd = __ldg(&dst[e]);
        float nrm = __ldg(&norm[e]);
        const float* frow = (float*)(smc + SM_FBUF) + (t >> 1) * FB_STRIDE + c0;
        const uint4* tsp = (const uint4*)(g_tsrc + (size_t)s * 128 + c0);
        const uint4* tdp = (const uint4*)(g_tdst + (size_t)dd * 128 + c0);

        float pd[16];
#pragma unroll
        for (int d = 0; d < 16; ++d) pd[d] = 0.f;
        float ex[4], exn[4];
#pragma unroll
        for (int hl = 0; hl < 4; ++hl) {
            uint4 sa0 = __ldg(tsp + hl * 2), sa1 = __ldg(tsp + hl * 2 + 1);
            uint4 da0 = __ldg(tdp + hl * 2), da1 = __ldg(tdp + hl * 2 + 1);
            uint32_t sw[8] = {sa0.x, sa0.y, sa0.z, sa0.w, sa1.x, sa1.y, sa1.z, sa1.w};
            uint32_t dw[8] = {da0.x, da0.y, da0.z, da0.w, da1.x, da1.y, da1.z, da1.w};
            float lgv = 0.f;
#pragma unroll
            for (int j = 0; j < 4; ++j) {
                float4 dv = *(const float4*)(frow + hl * 16 + j * 4);
                float2 s01 = h2f2(sw[j * 2]), s23 = h2f2(sw[j * 2 + 1]);
                float2 d01 = h2f2(dw[j * 2]), d23 = h2f2(dw[j * 2 + 1]);
                int cb = c0 + hl * 16 + j * 4;
                float v0 = dv.x + s01.x + d01.x;
                float v1 = dv.y + s01.y + d01.y;
                float v2 = dv.z + s23.x + d23.x;
                float v3 = dv.w + s23.y + d23.y;
                v0 = (v0 > 0.f) ? v0 : 0.01f * v0;
                v1 = (v1 > 0.f) ? v1 : 0.01f * v1;
                v2 = (v2 > 0.f) ? v2 : 0.01f * v2;
                v3 = (v3 > 0.f) ? v3 : 0.01f * v3;
                v0 += bias_s[cb];
                v1 += bias_s[cb + 1];
                v2 += bias_s[cb + 2];
                v3 += bias_s[cb + 3];
                pd[j * 4]     += v0;
                pd[j * 4 + 1] += v1;
                pd[j * 4 + 2] += v2;
                pd[j * 4 + 3] += v3;
                lgv += v0 * ws_s[j * 4] + v1 * ws_s[j * 4 + 1]
                     + v2 * ws_s[j * 4 + 2] + v3 * ws_s[j * 4 + 3];
            }
            ex[hl]  = __expf(lgv);
            exn[hl] = ex[hl] * nrm;
        }
#pragma unroll
        for (int d = 0; d < 16; ++d) pd[d] += __shfl_xor_sync(0xffffffffu, pd[d], 1);
        if (!half) {
#pragma unroll
            for (int qj = 0; qj < 4; ++qj)
                ((float4*)(out2 + (size_t)e * DEF))[qj] =
                    make_float4(pd[qj * 4], pd[qj * 4 + 1], pd[qj * 4 + 2], pd[qj * 4 + 3]);
        }
        ((float4*)g_a)[(size_t)e * 2 + half] = make_float4(exn[0], exn[1], exn[2], exn[3]);
#pragma unroll
        for (int hl = 0; hl < 4; ++hl)
            atomicAdd(&g_den[(size_t)dd * NHEAD + h0 + hl], ex[hl]);
        __syncthreads();
    }
}

// ---------------- message passing --------------------------------------------
__global__ void k_msg(const int* __restrict__ src, const int* __restrict__ dst,
                      float* __restrict__ out1) {
    int gid = blockIdx.x * blockDim.x + threadIdx.x;
    int e = gid >> 4, d = gid & 15;
    if (e >= EE) return;
    int s  = __ldg(&src[e]);
    int dd = __ldg(&dst[e]);
    float acc = 0.f;
#pragma unroll
    for (int h = 0; h < NHEAD; ++h) {
        float w = __fdividef(g_a[(size_t)e * NHEAD + h],
                             g_den[(size_t)dd * NHEAD + h]);
        acc += w * __half2float(g_hnode[(size_t)s * 128 + h * DNF + d]);
    }
    atomicAdd(&out1[(size_t)dd * DNF + d], acc);
}

// ---------------- launch ------------------------------------------------------
extern "C" void kernel_launch(void* const* d_in, const int* in_sizes, int n_in,
                              void* d_out, int out_size) {
    const float* nfeats  = (const float*)d_in[0];
    const float* efeats  = (const float*)d_in[1];
    const float* norm    = (const float*)d_in[2];
    const int*   src     = (const int*)d_in[3];
    const int*   dst     = (const int*)d_in[4];
    const float* W_ni    = (const float*)d_in[5];
    const float* W_nj    = (const float*)d_in[6];
    const float* W_fij   = (const float*)d_in[7];
    const float* W_edges = (const float*)d_in[8];
    const float* W_attn  = (const float*)d_in[9];
    const float* bias    = (const float*)d_in[10];
    const float* W_node  = (const float*)d_in[11];
    const float* b_node  = (const float*)d_in[12];

    float* out1 = (float*)d_out;
    float* out2 = out1 + (size_t)NN * DNF;

    cudaFuncSetAttribute(k_node_mma, cudaFuncAttributeMaxDynamicSharedMemorySize, SMN_TOTAL);
    cudaFuncSetAttribute(k_edge_mma, cudaFuncAttributeMaxDynamicSharedMemorySize, SM_TOTAL);

    k_init<<<3125, 256>>>(out1);
    k_weights<<<dim3(128, 4), 128>>>(W_edges, W_ni, W_nj, W_fij, W_node, W_attn);
    k_wconv<<<256, 256>>>();
    k_node_mma<<<148, 256, SMN_TOTAL>>>(nfeats, b_node);
    k_edge_mma<<<148, 256, SM_TOTAL>>>(efeats, src, dst, norm, bias, out2);
    k_msg<<<(EE * DNF + 255) / 256, 256>>>(src, dst, out1);
}

// round 9
// speedup vs baseline: 1.7797x; 1.1012x over previous
#include <cuda_runtime.h>
#include <cuda_fp16.h>
#include <cstring>
#include <cstdint>

#define NN 50000
#define EE 400000
#define NHEAD 8
#define DEF 16
#define DNF 16

// ---------------- device global scratch ------------------------------------
__device__ float g_N1t[128 * 128];   // (W1@W_ni)^T: [k][c]
__device__ float g_A2t[128 * 128];   // (W2@W_fij)^T
__device__ float g_N3t[128 * 128];   // (W3@W_nj)^T
__device__ float g_Wnt[128 * 128];   // W_node^T
__device__ float g_wsum[DEF];
// B operand as fp16 [n][k], row stride 136 elements
__device__ __half g_Bh[4 * 128 * 136];
__device__ __half g_tsrc[NN * 128];  // fp16 projected node tables
__device__ __half g_tdst[NN * 128];
__device__ __half g_hnode[NN * 128];
__device__ float g_a[EE * NHEAD];    // exp(logit) * norm
__device__ float g_den[NN * NHEAD];  // sum of raw exp(logit)

// ---------------- smem layouts (bytes) ---------------------------------------
#define RSTRIDE 272                 // 136 fp16 per row
#define AB_BYTES (128 * RSTRIDE)    // 34816
#define FB_STRIDE 132
#define FB_BYTES (128 * FB_STRIDE * 4)  // 67584

// edge kernel layout: A (34816) and fbuf (67584) overlay in one 67584 region
#define SM_BIAS 0
#define SM_WS   512
#define SM_A    1024
#define SM_AHI  SM_A
#define SM_FBUF SM_A
#define SM_BHI  (SM_A + FB_BYTES)        // 68608
#define SM_TOTAL (SM_BHI + AB_BYTES)     // 103424  (2 CTAs/SM)

// fused node kernel layout
#define SMN_BIAS 0
#define SMN_AHI  1024
#define SMN_B0   (SMN_AHI + AB_BYTES)           // 35840
#define SMN_TOTAL (SMN_B0 + 3 * AB_BYTES)       // 140288

// ---------------- small kernels ----------------------------------------------
__global__ void k_init(float* __restrict__ out1) {
    int i = blockIdx.x * blockDim.x + threadIdx.x;
    if (i < NN * NHEAD) g_den[i] = 0.f;
    if (i < NN * DNF)   out1[i] = 0.f;
}

__global__ void k_weights(const float* __restrict__ W_edges,
                          const float* __restrict__ W_ni,
                          const float* __restrict__ W_nj,
                          const float* __restrict__ W_fij,
                          const float* __restrict__ W_node,
                          const float* __restrict__ W_attn) {
    int k = blockIdx.x, c = threadIdx.x, m = blockIdx.y;
    if (m == 0) {
        float acc = 0.f;
        for (int j = 0; j < 128; ++j) acc += W_edges[c * 384 + j] * W_ni[j * 128 + k];
        g_N1t[k * 128 + c] = acc;
    } else if (m == 1) {
        float acc = 0.f;
        for (int j = 0; j < 128; ++j) acc += W_edges[c * 384 + 128 + j] * W_fij[j * 128 + k];
        g_A2t[k * 128 + c] = acc;
    } else if (m == 2) {
        float acc = 0.f;
        for (int j = 0; j < 128; ++j) acc += W_edges[c * 384 + 256 + j] * W_nj[j * 128 + k];
        g_N3t[k * 128 + c] = acc;
    } else {
        g_Wnt[k * 128 + c] = W_node[c * 128 + k];
        if (k == 0 && c < DEF) {
            float s = 0.f;
            for (int h = 0; h < NHEAD; ++h) s += W_attn[h * DEF + c];
            g_wsum[c] = s;
        }
    }
}

__global__ void k_wconv() {
    int idx = blockIdx.x * blockDim.x + threadIdx.x;  // 65536
    int m = idx >> 14, r = idx & 16383;
    int n = r >> 7, k = r & 127;                      // B[n][k] = Wt[k][n]
    const float* srcs[4] = {g_N1t, g_A2t, g_N3t, g_Wnt};
    g_Bh[m * 128 * 136 + n * 136 + k] = __float2half_rn(srcs[m][k * 128 + n]);
}

// ---------------- fp32 -> fp16 tile stage -------------------------------------
__device__ __forceinline__ uint4 cvt8(const float4 v0, const float4 v1) {
    unsigned hu[4];
    __half2 h0 = __floats2half2_rn(v0.x, v0.y);
    __half2 h1 = __floats2half2_rn(v0.z, v0.w);
    __half2 h2 = __floats2half2_rn(v1.x, v1.y);
    __half2 h3 = __floats2half2_rn(v1.z, v1.w);
    memcpy(&hu[0], &h0, 4);
    memcpy(&hu[1], &h1, 4);
    memcpy(&hu[2], &h2, 4);
    memcpy(&hu[3], &h3, 4);
    return make_uint4(hu[0], hu[1], hu[2], hu[3]);
}

__device__ __forceinline__ void load_tile(char* smc, int ahioff,
                                          const float* __restrict__ srcp,
                                          int base, int limit, int t) {
    for (int i = t; i < 2048; i += 256) {
        int row = i >> 4, col = (i & 15) * 8;
        int gr = base + row;
        float4 v0, v1;
        if (gr < limit) {
            v0 = __ldg((const float4*)(srcp + (size_t)gr * 128 + col));
            v1 = __ldg((const float4*)(srcp + (size_t)gr * 128 + col + 4));
        } else {
            v0 = make_float4(0.f, 0.f, 0.f, 0.f); v1 = v0;
        }
        *(uint4*)(smc + ahioff + row * RSTRIDE + col * 2) = cvt8(v0, v1);
    }
}

// ---------------- mma.sync fp16 single-pass GEMM core --------------------------
__device__ __forceinline__ void mma16816(float (&d)[4], const uint32_t (&a)[4],
                                         const uint32_t (&b)[2]) {
    asm("mma.sync.aligned.m16n8k16.row.col.f32.f16.f16.f32 "
        "{%0,%1,%2,%3}, {%4,%5,%6,%7}, {%8,%9}, {%0,%1,%2,%3};"
        : "+f"(d[0]), "+f"(d[1]), "+f"(d[2]), "+f"(d[3])
        : "r"(a[0]), "r"(a[1]), "r"(a[2]), "r"(a[3]), "r"(b[0]), "r"(b[1]));
}

__device__ __forceinline__ uint32_t lds32(const char* base, int r, int k) {
    return *(const uint32_t*)(base + r * RSTRIDE + k * 2);
}

// block tile 128x128, warp tile 64x32; D = A * B, single fp16 pass
__device__ __forceinline__ void mm_one(const char* Ahi, const char* Bhi,
                                       int warp, int lane, float (&acc)[4][4][4]) {
    int warpm = warp & 1, warpn = warp >> 1;
    int q = lane >> 2, tid = lane & 3;

#pragma unroll
    for (int mt = 0; mt < 4; ++mt)
#pragma unroll
        for (int nt = 0; nt < 4; ++nt)
#pragma unroll
            for (int j = 0; j < 4; ++j) acc[mt][nt][j] = 0.f;

#pragma unroll
    for (int k0 = 0; k0 < 8; ++k0) {
        int kk = k0 * 16 + 2 * tid;
        uint32_t ahi[4][4], bhi[4][2];
#pragma unroll
        for (int mt = 0; mt < 4; ++mt) {
            int r = warpm * 64 + mt * 16 + q;
            ahi[mt][0] = lds32(Ahi, r, kk);
            ahi[mt][1] = lds32(Ahi, r + 8, kk);
            ahi[mt][2] = lds32(Ahi, r, kk + 8);
            ahi[mt][3] = lds32(Ahi, r + 8, kk + 8);
        }
#pragma unroll
        for (int nt = 0; nt < 4; ++nt) {
            int n = warpn * 32 + nt * 8 + q;
            bhi[nt][0] = lds32(Bhi, n, kk);
            bhi[nt][1] = lds32(Bhi, n, kk + 8);
        }
#pragma unroll
        for (int mt = 0; mt < 4; ++mt)
#pragma unroll
            for (int nt = 0; nt < 4; ++nt) mma16816(acc[mt][nt], ahi[mt], bhi[nt]);
    }
}

__device__ __forceinline__ void dump_acc(char* smc, int warp, int lane,
                                         const float (&acc)[4][4][4]) {
    int warpm = warp & 1, warpn = warp >> 1;
    int q = lane >> 2, tid = lane & 3;
    float* fb = (float*)(smc + SM_FBUF);
#pragma unroll
    for (int mt = 0; mt < 4; ++mt) {
        int r = warpm * 64 + mt * 16 + q;
#pragma unroll
        for (int nt = 0; nt < 4; ++nt) {
            int c = warpn * 32 + nt * 8 + 2 * tid;
            *(float2*)&fb[r * FB_STRIDE + c]       = make_float2(acc[mt][nt][0], acc[mt][nt][1]);
            *(float2*)&fb[(r + 8) * FB_STRIDE + c] = make_float2(acc[mt][nt][2], acc[mt][nt][3]);
        }
    }
}

// ---------------- fused node GEMMs: t_src / t_dst / h_node --------------------
__global__ void __launch_bounds__(256, 1)
k_node_mma(const float* __restrict__ nfeats, const float* __restrict__ b_node) {
    extern __shared__ char smc[];
    int t = threadIdx.x, warp = t >> 5, lane = t & 31;
    int warpm = warp & 1, warpn = warp >> 1;
    int q = lane >> 2, tid = lane & 3;

    // stage the 3 B operands (mats 0: tsrc, 2: tdst, 3: hnode)
    for (int i = t; i < 2176; i += 256) {
        ((uint4*)(smc + SMN_B0))[i]                = ((const uint4*)(g_Bh + 0 * 128 * 136))[i];
        ((uint4*)(smc + SMN_B0 + AB_BYTES))[i]     = ((const uint4*)(g_Bh + 2 * 128 * 136))[i];
        ((uint4*)(smc + SMN_B0 + 2 * AB_BYTES))[i] = ((const uint4*)(g_Bh + 3 * 128 * 136))[i];
    }
    float* bias_s = (float*)(smc + SMN_BIAS);
    for (int i = t; i < 128; i += 256) bias_s[i] = __ldg(&b_node[i]);

    const int ntiles = (NN + 127) / 128;   // 391
    for (int tile = blockIdx.x; tile < ntiles; tile += gridDim.x) {
        int n0 = tile * 128;
        load_tile(smc, SMN_AHI, nfeats, n0, NN, t);
        __syncthreads();
#pragma unroll 1
        for (int mat = 0; mat < 3; ++mat) {
            __half* OUT = (mat == 0) ? g_tsrc : (mat == 1 ? g_tdst : g_hnode);
            float acc[4][4][4];
            mm_one(smc + SMN_AHI, smc + SMN_B0 + mat * AB_BYTES, warp, lane, acc);
            // direct fragment -> fp16 gmem store
#pragma unroll
            for (int mt = 0; mt < 4; ++mt) {
                int rr = warpm * 64 + mt * 16 + q;
#pragma unroll
                for (int nt = 0; nt < 4; ++nt) {
                    int cc = warpn * 32 + nt * 8 + 2 * tid;
                    float b0 = 0.f, b1 = 0.f;
                    if (mat == 2) { b0 = bias_s[cc]; b1 = bias_s[cc + 1]; }
                    int n1 = n0 + rr, n2 = n1 + 8;
                    if (n1 < NN)
                        *(__half2*)(OUT + (size_t)n1 * 128 + cc) =
                            __floats2half2_rn(acc[mt][nt][0] + b0, acc[mt][nt][1] + b1);
                    if (n2 < NN)
                        *(__half2*)(OUT + (size_t)n2 * 128 + cc) =
                            __floats2half2_rn(acc[mt][nt][2] + b0, acc[mt][nt][3] + b1);
                }
            }
        }
        __syncthreads();   // all reads of A done before next load_tile
    }
}

// ---------------- fused edge kernel ------------------------------------------
__device__ __forceinline__ float2 h2f2(uint32_t u) {
    __half2 h;
    memcpy(&h, &u, 4);
    return __half22float2(h);
}

__global__ void __launch_bounds__(256, 2)
k_edge_mma(const float* __restrict__ efeats, const int* __restrict__ src,
           const int* __restrict__ dst, const float* __restrict__ norm,
           const float* __restrict__ bias, float* __restrict__ out2) {
    extern __shared__ char smc[];
    int t = threadIdx.x, warp = t >> 5, lane = t & 31;

    const uint4* bh = (const uint4*)(g_Bh + 1 * 128 * 136);
    for (int i = t; i < 2176; i += 256)
        ((uint4*)(smc + SM_BHI))[i] = bh[i];
    float* bias_s = (float*)(smc + SM_BIAS);
    float* ws_s   = (float*)(smc + SM_WS);
    for (int i = t; i < 128; i += 256) bias_s[i] = __ldg(&bias[i]);
    if (t < DEF) ws_s[t] = g_wsum[t];

    const int ntiles = EE / 128;   // 3125 exact
    for (int tile = blockIdx.x; tile < ntiles; tile += gridDim.x) {
        int e0 = tile * 128;
        load_tile(smc, SM_AHI, efeats, e0, 0x7fffffff, t);
        __syncthreads();
        float acc[4][4][4];
        mm_one(smc + SM_AHI, smc + SM_BHI, warp, lane, acc);
        __syncthreads();
        dump_acc(smc, warp, lane, acc);
        __syncthreads();

        // epilogue: 2 threads per edge row (halves of 128 cols = 4 heads each)
        int e = e0 + (t >> 1);
        int half = t & 1;
        int c0 = half * 64, h0 = half * 4;
        int s  = __ldg(&src[e]);
        int dd = __ldg(&dst[e]);
        float nrm = __ldg(&norm[e]);
        const float* frow = (float*)(smc + SM_FBUF) + (t >> 1) * FB_STRIDE + c0;
        const uint4* tsp = (const uint4*)(g_tsrc + (size_t)s * 128 + c0);
        const uint4* tdp = (const uint4*)(g_tdst + (size_t)dd * 128 + c0);

        float pd[16];
#pragma unroll
        for (int d = 0; d < 16; ++d) pd[d] = 0.f;
        float ex[4], exn[4];
#pragma unroll
        for (int hl = 0; hl < 4; ++hl) {
            uint4 sa0 = __ldg(tsp + hl * 2), sa1 = __ldg(tsp + hl * 2 + 1);
            uint4 da0 = __ldg(tdp + hl * 2), da1 = __ldg(tdp + hl * 2 + 1);
            uint32_t sw[8] = {sa0.x, sa0.y, sa0.z, sa0.w, sa1.x, sa1.y, sa1.z, sa1.w};
            uint32_t dw[8] = {da0.x, da0.y, da0.z, da0.w, da1.x, da1.y, da1.z, da1.w};
            float lgv = 0.f;
#pragma unroll
            for (int j = 0; j < 4; ++j) {
                float4 dv = *(const float4*)(frow + hl * 16 + j * 4);
                float2 s01 = h2f2(sw[j * 2]), s23 = h2f2(sw[j * 2 + 1]);
                float2 d01 = h2f2(dw[j * 2]), d23 = h2f2(dw[j * 2 + 1]);
                int cb = c0 + hl * 16 + j * 4;
                float v0 = dv.x + s01.x + d01.x;
                float v1 = dv.y + s01.y + d01.y;
                float v2 = dv.z + s23.x + d23.x;
                float v3 = dv.w + s23.y + d23.y;
                v0 = (v0 > 0.f) ? v0 : 0.01f * v0;
                v1 = (v1 > 0.f) ? v1 : 0.01f * v1;
                v2 = (v2 > 0.f) ? v2 : 0.01f * v2;
                v3 = (v3 > 0.f) ? v3 : 0.01f * v3;
                v0 += bias_s[cb];
                v1 += bias_s[cb + 1];
                v2 += bias_s[cb + 2];
                v3 += bias_s[cb + 3];
                pd[j * 4]     += v0;
                pd[j * 4 + 1] += v1;
                pd[j * 4 + 2] += v2;
                pd[j * 4 + 3] += v3;
                lgv += v0 * ws_s[j * 4] + v1 * ws_s[j * 4 + 1]
                     + v2 * ws_s[j * 4 + 2] + v3 * ws_s[j * 4 + 3];
            }
            ex[hl]  = __expf(lgv);
            exn[hl] = ex[hl] * nrm;
        }
#pragma unroll
        for (int d = 0; d < 16; ++d) pd[d] += __shfl_xor_sync(0xffffffffu, pd[d], 1);
        if (!half) {
#pragma unroll
            for (int qj = 0; qj < 4; ++qj)
                ((float4*)(out2 + (size_t)e * DEF))[qj] =
                    make_float4(pd[qj * 4], pd[qj * 4 + 1], pd[qj * 4 + 2], pd[qj * 4 + 3]);
        }
        ((float4*)g_a)[(size_t)e * 2 + half] = make_float4(exn[0], exn[1], exn[2], exn[3]);
#pragma unroll
        for (int hl = 0; hl < 4; ++hl)
            atomicAdd(&g_den[(size_t)dd * NHEAD + h0 + hl], ex[hl]);
        __syncthreads();
    }
}

// ---------------- message passing --------------------------------------------
__global__ void k_msg(const int* __restrict__ src, const int* __restrict__ dst,
                      float* __restrict__ out1) {
    int gid = blockIdx.x * blockDim.x + threadIdx.x;
    int e = gid >> 4, d = gid & 15;
    if (e >= EE) return;
    int s  = __ldg(&src[e]);
    int dd = __ldg(&dst[e]);
    float acc = 0.f;
#pragma unroll
    for (int h = 0; h < NHEAD; ++h) {
        float w = __fdividef(g_a[(size_t)e * NHEAD + h],
                             g_den[(size_t)dd * NHEAD + h]);
        acc += w * __half2float(g_hnode[(size_t)s * 128 + h * DNF + d]);
    }
    atomicAdd(&out1[(size_t)dd * DNF + d], acc);
}

// ---------------- launch ------------------------------------------------------
extern "C" void kernel_launch(void* const* d_in, const int* in_sizes, int n_in,
                              void* d_out, int out_size) {
    const float* nfeats  = (const float*)d_in[0];
    const float* efeats  = (const float*)d_in[1];
    const float* norm    = (const float*)d_in[2];
    const int*   src     = (const int*)d_in[3];
    const int*   dst     = (const int*)d_in[4];
    const float* W_ni    = (const float*)d_in[5];
    const float* W_nj    = (const float*)d_in[6];
    const float* W_fij   = (const float*)d_in[7];
    const float* W_edges = (const float*)d_in[8];
    const float* W_attn  = (const float*)d_in[9];
    const float* bias    = (const float*)d_in[10];
    const float* W_node  = (const float*)d_in[11];
    const float* b_node  = (const float*)d_in[12];

    float* out1 = (float*)d_out;
    float* out2 = out1 + (size_t)NN * DNF;

    cudaFuncSetAttribute(k_node_mma, cudaFuncAttributeMaxDynamicSharedMemorySize, SMN_TOTAL);
    cudaFuncSetAttribute(k_edge_mma, cudaFuncAttributeMaxDynamicSharedMemorySize, SM_TOTAL);

    k_init<<<3125, 256>>>(out1);
    k_weights<<<dim3(128, 4), 128>>>(W_edges, W_ni, W_nj, W_fij, W_node, W_attn);
    k_wconv<<<256, 256>>>();
    k_node_mma<<<148, 256, SMN_TOTAL>>>(nfeats, b_node);
    k_edge_mma<<<296, 256, SM_TOTAL>>>(efeats, src, dst, norm, bias, out2);
    k_msg<<<(EE * DNF + 255) / 256, 256>>>(src, dst, out1);
}

// round 10
// speedup vs baseline: 1.7808x; 1.0006x over previous
#include <cuda_runtime.h>
#include <cuda_fp16.h>
#include <cstring>
#include <cstdint>

#define NN 50000
#define EE 400000
#define NHEAD 8
#define DEF 16
#define DNF 16

// ---------------- device global scratch ------------------------------------
__device__ float g_wsum[DEF];
// B operands as fp16 [n][k], row stride 136 (slot 0:tsrc 1:edge 2:tdst 3:hnode)
__device__ __half g_Bh[4 * 128 * 136];
__device__ __half g_tsrc[NN * 128];
__device__ __half g_tdst[NN * 128];
__device__ __half g_hnode[NN * 128];
__device__ float g_a[EE * NHEAD];    // exp(logit) * norm
__device__ float g_den[NN * NHEAD];  // sum of raw exp(logit)

// ---------------- smem layouts (bytes) ---------------------------------------
#define RSTRIDE 272                 // 136 fp16 per row
#define AB_BYTES (128 * RSTRIDE)    // 34816
#define FB_STRIDE 132
#define FB_BYTES (128 * FB_STRIDE * 4)  // 67584

// edge kernel layout: A (34816) and fbuf (67584) overlay
#define SM_BIAS 0
#define SM_WS   512
#define SM_A    1024
#define SM_AHI  SM_A
#define SM_FBUF SM_A
#define SM_BHI  (SM_A + FB_BYTES)        // 68608
#define SM_TOTAL (SM_BHI + AB_BYTES)     // 103424  (2 CTAs/SM)

// fused node kernel layout
#define SMN_BIAS 0
#define SMN_AHI  1024
#define SMN_B0   (SMN_AHI + AB_BYTES)           // 35840
#define SMN_TOTAL (SMN_B0 + 3 * AB_BYTES)       // 140288

// ---------------- helpers ------------------------------------------------------
__device__ __forceinline__ uint32_t smem_u32(const void* p) {
    uint32_t a;
    asm("{ .reg .u64 t; cvta.to.shared.u64 t, %1; cvt.u32.u64 %0, t; }" : "=r"(a) : "l"(p));
    return a;
}
__device__ __forceinline__ float2 h2f2(uint32_t u) {
    __half2 h;
    memcpy(&h, &u, 4);
    return __half22float2(h);
}

// ---------------- small kernels ----------------------------------------------
__global__ void k_init(float* __restrict__ out1) {
    int i = blockIdx.x * blockDim.x + threadIdx.x;
    if (i < NN * NHEAD) g_den[i] = 0.f;
    if (i < NN * DNF)   out1[i] = 0.f;
}

// fused: combined weights -> fp16 B operands directly
__global__ void k_wb(const float* __restrict__ W_edges,
                     const float* __restrict__ W_ni,
                     const float* __restrict__ W_nj,
                     const float* __restrict__ W_fij,
                     const float* __restrict__ W_node,
                     const float* __restrict__ W_attn) {
    int k = blockIdx.x, c = threadIdx.x, m = blockIdx.y;
    float acc = 0.f;
    if (m == 0) {
        for (int j = 0; j < 128; ++j) acc += W_edges[c * 384 + j] * W_ni[j * 128 + k];
    } else if (m == 1) {
        for (int j = 0; j < 128; ++j) acc += W_edges[c * 384 + 128 + j] * W_fij[j * 128 + k];
    } else if (m == 2) {
        for (int j = 0; j < 128; ++j) acc += W_edges[c * 384 + 256 + j] * W_nj[j * 128 + k];
    } else {
        acc = W_node[c * 128 + k];
        if (k == 0 && c < DEF) {
            float s = 0.f;
            for (int h = 0; h < NHEAD; ++h) s += W_attn[h * DEF + c];
            g_wsum[c] = s;
        }
    }
    g_Bh[m * 128 * 136 + c * 136 + k] = __float2half_rn(acc);
}

// ---------------- fp32 -> fp16 tile stage -------------------------------------
__device__ __forceinline__ uint4 cvt8(const float4 v0, const float4 v1) {
    unsigned hu[4];
    __half2 h0 = __floats2half2_rn(v0.x, v0.y);
    __half2 h1 = __floats2half2_rn(v0.z, v0.w);
    __half2 h2 = __floats2half2_rn(v1.x, v1.y);
    __half2 h3 = __floats2half2_rn(v1.z, v1.w);
    memcpy(&hu[0], &h0, 4);
    memcpy(&hu[1], &h1, 4);
    memcpy(&hu[2], &h2, 4);
    memcpy(&hu[3], &h3, 4);
    return make_uint4(hu[0], hu[1], hu[2], hu[3]);
}

__device__ __forceinline__ void load_tile(char* smc, int ahioff,
                                          const float* __restrict__ srcp,
                                          int base, int limit, int t) {
    for (int i = t; i < 2048; i += 256) {
        int row = i >> 4, col = (i & 15) * 8;
        int gr = base + row;
        float4 v0, v1;
        if (gr < limit) {
            v0 = __ldg((const float4*)(srcp + (size_t)gr * 128 + col));
            v1 = __ldg((const float4*)(srcp + (size_t)gr * 128 + col + 4));
        } else {
            v0 = make_float4(0.f, 0.f, 0.f, 0.f); v1 = v0;
        }
        *(uint4*)(smc + ahioff + row * RSTRIDE + col * 2) = cvt8(v0, v1);
    }
}

// ---------------- mma core (ldmatrix + single fp16 pass) -----------------------
__device__ __forceinline__ void mma16816(float (&d)[4], const uint32_t (&a)[4],
                                         uint32_t b0, uint32_t b1) {
    asm("mma.sync.aligned.m16n8k16.row.col.f32.f16.f16.f32 "
        "{%0,%1,%2,%3}, {%4,%5,%6,%7}, {%8,%9}, {%0,%1,%2,%3};"
        : "+f"(d[0]), "+f"(d[1]), "+f"(d[2]), "+f"(d[3])
        : "r"(a[0]), "r"(a[1]), "r"(a[2]), "r"(a[3]), "r"(b0), "r"(b1));
}

__device__ __forceinline__ void ldmat4(uint32_t (&r)[4], uint32_t addr) {
    asm volatile("ldmatrix.sync.aligned.m8n8.x4.shared.b16 {%0,%1,%2,%3}, [%4];"
                 : "=r"(r[0]), "=r"(r[1]), "=r"(r[2]), "=r"(r[3]) : "r"(addr));
}

// block tile 128x128, warp tile 64x32
__device__ __forceinline__ void mm_one(uint32_t aBase, uint32_t bBase,
                                       int warp, int lane, float (&acc)[4][4][4]) {
    int warpm = warp & 1, warpn = warp >> 1;
    uint32_t a_addr = aBase + (uint32_t)((warpm * 64 + (lane & 15)) * RSTRIDE + ((lane >> 4) << 4));
    uint32_t b_addr = bBase + (uint32_t)((warpn * 32 + (lane & 7) + ((lane >> 4) << 3)) * RSTRIDE
                                         + (((lane >> 3) & 1) << 4));

#pragma unroll
    for (int mt = 0; mt < 4; ++mt)
#pragma unroll
        for (int nt = 0; nt < 4; ++nt)
#pragma unroll
            for (int j = 0; j < 4; ++j) acc[mt][nt][j] = 0.f;

#pragma unroll
    for (int k0 = 0; k0 < 8; ++k0) {
        uint32_t ko = k0 * 32;
        uint32_t ahi[4][4], bhi[2][4];
#pragma unroll
        for (int mt = 0; mt < 4; ++mt)
            ldmat4(ahi[mt], a_addr + mt * 16 * RSTRIDE + ko);
#pragma unroll
        for (int g = 0; g < 2; ++g)
            ldmat4(bhi[g], b_addr + g * 16 * RSTRIDE + ko);
#pragma unroll
        for (int mt = 0; mt < 4; ++mt)
#pragma unroll
            for (int nt = 0; nt < 4; ++nt)
                mma16816(acc[mt][nt], ahi[mt],
                         bhi[nt >> 1][(nt & 1) * 2], bhi[nt >> 1][(nt & 1) * 2 + 1]);
    }
}

__device__ __forceinline__ void dump_acc(char* smc, int warp, int lane,
                                         const float (&acc)[4][4][4]) {
    int warpm = warp & 1, warpn = warp >> 1;
    int q = lane >> 2, tid = lane & 3;
    float* fb = (float*)(smc + SM_FBUF);
#pragma unroll
    for (int mt = 0; mt < 4; ++mt) {
        int r = warpm * 64 + mt * 16 + q;
#pragma unroll
        for (int nt = 0; nt < 4; ++nt) {
            int c = warpn * 32 + nt * 8 + 2 * tid;
            *(float2*)&fb[r * FB_STRIDE + c]       = make_float2(acc[mt][nt][0], acc[mt][nt][1]);
            *(float2*)&fb[(r + 8) * FB_STRIDE + c] = make_float2(acc[mt][nt][2], acc[mt][nt][3]);
        }
    }
}

// ---------------- fused node GEMMs: t_src / t_dst / h_node --------------------
__global__ void __launch_bounds__(256, 1)
k_node_mma(const float* __restrict__ nfeats, const float* __restrict__ b_node) {
    extern __shared__ char smc[];
    uint32_t sbase = smem_u32(smc);
    int t = threadIdx.x, warp = t >> 5, lane = t & 31;
    int warpm = warp & 1, warpn = warp >> 1;
    int q = lane >> 2, tid = lane & 3;

    // stage the 3 B operands (slots 0: tsrc, 2: tdst, 3: hnode)
    for (int i = t; i < 2176; i += 256) {
        ((uint4*)(smc + SMN_B0))[i]                = ((const uint4*)(g_Bh + 0 * 128 * 136))[i];
        ((uint4*)(smc + SMN_B0 + AB_BYTES))[i]     = ((const uint4*)(g_Bh + 2 * 128 * 136))[i];
        ((uint4*)(smc + SMN_B0 + 2 * AB_BYTES))[i] = ((const uint4*)(g_Bh + 3 * 128 * 136))[i];
    }
    float* bias_s = (float*)(smc + SMN_BIAS);
    for (int i = t; i < 128; i += 256) bias_s[i] = __ldg(&b_node[i]);

    const int ntiles = (NN + 127) / 128;   // 391
    for (int tile = blockIdx.x; tile < ntiles; tile += gridDim.x) {
        int n0 = tile * 128;
        load_tile(smc, SMN_AHI, nfeats, n0, NN, t);
        __syncthreads();
#pragma unroll 1
        for (int mat = 0; mat < 3; ++mat) {
            __half* OUT = (mat == 0) ? g_tsrc : (mat == 1 ? g_tdst : g_hnode);
            float acc[4][4][4];
            mm_one(sbase + SMN_AHI, sbase + SMN_B0 + mat * AB_BYTES, warp, lane, acc);
            // direct fragment -> fp16 gmem store
#pragma unroll
            for (int mt = 0; mt < 4; ++mt) {
                int rr = warpm * 64 + mt * 16 + q;
#pragma unroll
                for (int nt = 0; nt < 4; ++nt) {
                    int cc = warpn * 32 + nt * 8 + 2 * tid;
                    float b0 = 0.f, b1 = 0.f;
                    if (mat == 2) { b0 = bias_s[cc]; b1 = bias_s[cc + 1]; }
                    int n1 = n0 + rr, n2 = n1 + 8;
                    if (n1 < NN)
                        *(__half2*)(OUT + (size_t)n1 * 128 + cc) =
                            __floats2half2_rn(acc[mt][nt][0] + b0, acc[mt][nt][1] + b1);
                    if (n2 < NN)
                        *(__half2*)(OUT + (size_t)n2 * 128 + cc) =
                            __floats2half2_rn(acc[mt][nt][2] + b0, acc[mt][nt][3] + b1);
                }
            }
        }
        __syncthreads();   // all reads of A done before next load_tile
    }
}

// ---------------- fused edge kernel ------------------------------------------
__global__ void __launch_bounds__(256, 2)
k_edge_mma(const float* __restrict__ efeats, const int* __restrict__ src,
           const int* __restrict__ dst, const float* __restrict__ norm,
           const float* __restrict__ bias, float* __restrict__ out2) {
    extern __shared__ char smc[];
    uint32_t sbase = smem_u32(smc);
    int t = threadIdx.x, warp = t >> 5, lane = t & 31;

    const uint4* bh = (const uint4*)(g_Bh + 1 * 128 * 136);
    for (int i = t; i < 2176; i += 256)
        ((uint4*)(smc + SM_BHI))[i] = bh[i];
    float* bias_s = (float*)(smc + SM_BIAS);
    float* ws_s   = (float*)(smc + SM_WS);
    for (int i = t; i < 128; i += 256) bias_s[i] = __ldg(&bias[i]);
    if (t < DEF) ws_s[t] = g_wsum[t];

    const int ntiles = EE / 128;   // 3125 exact
    for (int tile = blockIdx.x; tile < ntiles; tile += gridDim.x) {
        int e0 = tile * 128;
        load_tile(smc, SM_AHI, efeats, e0, 0x7fffffff, t);
        __syncthreads();
        float acc[4][4][4];
        mm_one(sbase + SM_AHI, sbase + SM_BHI, warp, lane, acc);
        __syncthreads();
        dump_acc(smc, warp, lane, acc);
        __syncthreads();

        // epilogue: 2 threads per edge row (halves of 128 cols = 4 heads each)
        int e = e0 + (t >> 1);
        int half = t & 1;
        int c0 = half * 64, h0 = half * 4;
        int s  = __ldg(&src[e]);
        int dd = __ldg(&dst[e]);
        float nrm = __ldg(&norm[e]);
        const float* frow = (float*)(smc + SM_FBUF) + (t >> 1) * FB_STRIDE + c0;
        const uint4* tsp = (const uint4*)(g_tsrc + (size_t)s * 128 + c0);
        const uint4* tdp = (const uint4*)(g_tdst + (size_t)dd * 128 + c0);

        float pd[16];
#pragma unroll
        for (int d = 0; d < 16; ++d) pd[d] = 0.f;
        float ex[4], exn[4];
#pragma unroll
        for (int hl = 0; hl < 4; ++hl) {
            uint4 sa0 = __ldg(tsp + hl * 2), sa1 = __ldg(tsp + hl * 2 + 1);
            uint4 da0 = __ldg(tdp + hl * 2), da1 = __ldg(tdp + hl * 2 + 1);
            uint32_t sw[8] = {sa0.x, sa0.y, sa0.z, sa0.w, sa1.x, sa1.y, sa1.z, sa1.w};
            uint32_t dw[8] = {da0.x, da0.y, da0.z, da0.w, da1.x, da1.y, da1.z, da1.w};
            float lgv = 0.f;
#pragma unroll
            for (int j = 0; j < 4; ++j) {
                float4 dv = *(const float4*)(frow + hl * 16 + j * 4);
                float2 s01 = h2f2(sw[j * 2]), s23 = h2f2(sw[j * 2 + 1]);
                float2 d01 = h2f2(dw[j * 2]), d23 = h2f2(dw[j * 2 + 1]);
                int cb = c0 + hl * 16 + j * 4;
                float v0 = dv.x + s01.x + d01.x;
                float v1 = dv.y + s01.y + d01.y;
                float v2 = dv.z + s23.x + d23.x;
                float v3 = dv.w + s23.y + d23.y;
                v0 = (v0 > 0.f) ? v0 : 0.01f * v0;
                v1 = (v1 > 0.f) ? v1 : 0.01f * v1;
                v2 = (v2 > 0.f) ? v2 : 0.01f * v2;
                v3 = (v3 > 0.f) ? v3 : 0.01f * v3;
                v0 += bias_s[cb];
                v1 += bias_s[cb + 1];
                v2 += bias_s[cb + 2];
                v3 += bias_s[cb + 3];
                pd[j * 4]     += v0;
                pd[j * 4 + 1] += v1;
                pd[j * 4 + 2] += v2;
                pd[j * 4 + 3] += v3;
                lgv += v0 * ws_s[j * 4] + v1 * ws_s[j * 4 + 1]
                     + v2 * ws_s[j * 4 + 2] + v3 * ws_s[j * 4 + 3];
            }
            ex[hl]  = __expf(lgv);
            exn[hl] = ex[hl] * nrm;
        }
#pragma unroll
        for (int d = 0; d < 16; ++d) pd[d] += __shfl_xor_sync(0xffffffffu, pd[d], 1);
        if (!half) {
#pragma unroll
            for (int qj = 0; qj < 4; ++qj)
                ((float4*)(out2 + (size_t)e * DEF))[qj] =
                    make_float4(pd[qj * 4], pd[qj * 4 + 1], pd[qj * 4 + 2], pd[qj * 4 + 3]);
        }
        ((float4*)g_a)[(size_t)e * 2 + half] = make_float4(exn[0], exn[1], exn[2], exn[3]);
#pragma unroll
        for (int hl = 0; hl < 4; ++hl)
            atomicAdd(&g_den[(size_t)dd * NHEAD + h0 + hl], ex[hl]);
        __syncthreads();
    }
}

// ---------------- message passing (coalesced + shuffle reduce) ----------------
// warp = 2 edges; lane t16 loads one uint4 (head h = t16>>1, dims (t16&1)*8..+7)
__global__ void k_msg(const int* __restrict__ src, const int* __restrict__ dst,
                      float* __restrict__ out1) {
    int gid = blockIdx.x * blockDim.x + threadIdx.x;
    int lane = gid & 31;
    int e = (gid >> 5) * 2 + (lane >> 4);
    if (e >= EE) return;                 // grid exact: never diverges
    int t16 = lane & 15;
    int h = t16 >> 1;
    int s  = __ldg(&src[e]);
    int dd = __ldg(&dst[e]);
    float w = __fdividef(__ldg(&g_a[(size_t)e * NHEAD + h]),
                         __ldg(&g_den[(size_t)dd * NHEAD + h]));
    uint4 hv = __ldg((const uint4*)(g_hnode + (size_t)s * 128) + t16);
    uint32_t hw[4] = {hv.x, hv.y, hv.z, hv.w};
    float p[8];
#pragma unroll
    for (int j = 0; j < 4; ++j) {
        float2 f = h2f2(hw[j]);
        p[2 * j]     = w * f.x;
        p[2 * j + 1] = w * f.y;
    }
    // reduce over the 3 head bits (lane bits 1..3)
#pragma unroll
    for (int m = 2; m <= 8; m <<= 1)
#pragma unroll
        for (int j = 0; j < 8; ++j)
            p[j] += __shfl_xor_sync(0xffffffffu, p[j], m);
    if ((lane & 14) == 0) {
        int dbase = (t16 & 1) * 8;
#pragma unroll
        for (int j = 0; j < 8; ++j)
            atomicAdd(&out1[(size_t)dd * DNF + dbase + j], p[j]);
    }
}

// ---------------- launch ------------------------------------------------------
extern "C" void kernel_launch(void* const* d_in, const int* in_sizes, int n_in,
                              void* d_out, int out_size) {
    const float* nfeats  = (const float*)d_in[0];
    const float* efeats  = (const float*)d_in[1];
    const float* norm    = (const float*)d_in[2];
    const int*   src     = (const int*)d_in[3];
    const int*   dst     = (const int*)d_in[4];
    const float* W_ni    = (const float*)d_in[5];
    const float* W_nj    = (const float*)d_in[6];
    const float* W_fij   = (const float*)d_in[7];
    const float* W_edges = (const float*)d_in[8];
    const float* W_attn  = (const float*)d_in[9];
    const float* bias    = (const float*)d_in[10];
    const float* W_node  = (const float*)d_in[11];
    const float* b_node  = (const float*)d_in[12];

    float* out1 = (float*)d_out;
    float* out2 = out1 + (size_t)NN * DNF;

    cudaFuncSetAttribute(k_node_mma, cudaFuncAttributeMaxDynamicSharedMemorySize, SMN_TOTAL);
    cudaFuncSetAttribute(k_edge_mma, cudaFuncAttributeMaxDynamicSharedMemorySize, SM_TOTAL);

    k_init<<<3125, 256>>>(out1);
    k_wb<<<dim3(128, 4), 128>>>(W_edges, W_ni, W_nj, W_fij, W_node, W_attn);
    k_node_mma<<<148, 256, SMN_TOTAL>>>(nfeats, b_node);
    k_edge_mma<<<296, 256, SM_TOTAL>>>(efeats, src, dst, norm, bias, out2);
    k_msg<<<(EE / 2) * 32 / 256, 256>>>(src, dst, out1);
}

// round 12
// speedup vs baseline: 1.8794x; 1.0554x over previous
#include <cuda_runtime.h>
#include <cuda_fp16.h>
#include <cstring>
#include <cstdint>

#define NN 50000
#define EE 400000
#define NHEAD 8
#define DEF 16
#define DNF 16

// ---------------- device global scratch ------------------------------------
__device__ float g_wsum[DEF];
// B operands as fp16 [n][k], row stride 136 (slot 0:tsrc 1:edge 2:tdst 3:hnode)
__device__ __half g_Bh[4 * 128 * 136];
__device__ __half g_tsrc[NN * 128];
__device__ __half g_tdst[NN * 128];
__device__ __half g_hnode[NN * 128];
__device__ float g_a[EE * NHEAD];    // exp(logit) * norm
__device__ float g_den[NN * NHEAD];  // sum of raw exp(logit)

// ---------------- smem layouts (bytes) ---------------------------------------
#define RSTRIDE 272                 // 136 fp16 per row
#define AB_BYTES (128 * RSTRIDE)    // 34816
#define FB_STRIDE 132
#define FB_BYTES (128 * FB_STRIDE * 4)  // 67584

// edge kernel layout: A (34816) and fbuf (67584) overlay
#define SM_BIAS 0
#define SM_WS   512
#define SM_A    1024
#define SM_AHI  SM_A
#define SM_FBUF SM_A
#define SM_BHI  (SM_A + FB_BYTES)        // 68608
#define SM_TOTAL (SM_BHI + AB_BYTES)     // 103424  (2 CTAs/SM)

// fused node kernel layout
#define SMN_BIAS 0
#define SMN_AHI  1024
#define SMN_B0   (SMN_AHI + AB_BYTES)           // 35840
#define SMN_TOTAL (SMN_B0 + 3 * AB_BYTES)       // 140288

// ---------------- helpers ------------------------------------------------------
__device__ __forceinline__ uint32_t smem_u32(const void* p) {
    uint32_t a;
    asm("{ .reg .u64 t; cvta.to.shared.u64 t, %1; cvt.u32.u64 %0, t; }" : "=r"(a) : "l"(p));
    return a;
}
__device__ __forceinline__ float2 h2f2(uint32_t u) {
    __half2 h;
    memcpy(&h, &u, 4);
    return __half22float2(h);
}
// 256-bit streaming load (this toolchain requires v8.b32 for L2::evict_first)
__device__ __forceinline__ void ldg_stream8(const float* p, float4& v0, float4& v1) {
    uint32_t r0, r1, r2, r3, r4, r5, r6, r7;
    asm volatile("ld.global.nc.L2::evict_first.v8.b32 {%0,%1,%2,%3,%4,%5,%6,%7}, [%8];"
                 : "=r"(r0), "=r"(r1), "=r"(r2), "=r"(r3),
                   "=r"(r4), "=r"(r5), "=r"(r6), "=r"(r7) : "l"(p));
    v0.x = __uint_as_float(r0); v0.y = __uint_as_float(r1);
    v0.z = __uint_as_float(r2); v0.w = __uint_as_float(r3);
    v1.x = __uint_as_float(r4); v1.y = __uint_as_float(r5);
    v1.z = __uint_as_float(r6); v1.w = __uint_as_float(r7);
}
__device__ __forceinline__ void stg_stream8(float* p, const float* v) {
    asm volatile("st.global.L2::evict_first.v8.b32 [%0], {%1,%2,%3,%4,%5,%6,%7,%8};"
                 :: "l"(p),
                    "r"(__float_as_uint(v[0])), "r"(__float_as_uint(v[1])),
                    "r"(__float_as_uint(v[2])), "r"(__float_as_uint(v[3])),
                    "r"(__float_as_uint(v[4])), "r"(__float_as_uint(v[5])),
                    "r"(__float_as_uint(v[6])), "r"(__float_as_uint(v[7])));
}
__device__ __forceinline__ void pf_l2(const void* p) {
    asm volatile("prefetch.global.L2 [%0];" :: "l"(p));
}

// ---------------- small kernels ----------------------------------------------
__global__ void k_init(float* __restrict__ out1) {
    int i = blockIdx.x * blockDim.x + threadIdx.x;
    if (i < NN * NHEAD) g_den[i] = 0.f;
    if (i < NN * DNF)   out1[i] = 0.f;
}

// fused: combined weights -> fp16 B operands directly
__global__ void k_wb(const float* __restrict__ W_edges,
                     const float* __restrict__ W_ni,
                     const float* __restrict__ W_nj,
                     const float* __restrict__ W_fij,
                     const float* __restrict__ W_node,
                     const float* __restrict__ W_attn) {
    int k = blockIdx.x, c = threadIdx.x, m = blockIdx.y;
    float acc = 0.f;
    if (m == 0) {
        for (int j = 0; j < 128; ++j) acc += W_edges[c * 384 + j] * W_ni[j * 128 + k];
    } else if (m == 1) {
        for (int j = 0; j < 128; ++j) acc += W_edges[c * 384 + 128 + j] * W_fij[j * 128 + k];
    } else if (m == 2) {
        for (int j = 0; j < 128; ++j) acc += W_edges[c * 384 + 256 + j] * W_nj[j * 128 + k];
    } else {
        acc = W_node[c * 128 + k];
        if (k == 0 && c < DEF) {
            float s = 0.f;
            for (int h = 0; h < NHEAD; ++h) s += W_attn[h * DEF + c];
            g_wsum[c] = s;
        }
    }
    g_Bh[m * 128 * 136 + c * 136 + k] = __float2half_rn(acc);
}

// ---------------- fp32 -> fp16 tile stage -------------------------------------
__device__ __forceinline__ uint4 cvt8(const float4 v0, const float4 v1) {
    unsigned hu[4];
    __half2 h0 = __floats2half2_rn(v0.x, v0.y);
    __half2 h1 = __floats2half2_rn(v0.z, v0.w);
    __half2 h2 = __floats2half2_rn(v1.x, v1.y);
    __half2 h3 = __floats2half2_rn(v1.z, v1.w);
    memcpy(&hu[0], &h0, 4);
    memcpy(&hu[1], &h1, 4);
    memcpy(&hu[2], &h2, 4);
    memcpy(&hu[3], &h3, 4);
    return make_uint4(hu[0], hu[1], hu[2], hu[3]);
}

// node variant: normal loads (nfeats re-used across 3 mats in-kernel)
__device__ __forceinline__ void load_tile(char* smc, int ahioff,
                                          const float* __restrict__ srcp,
                                          int base, int limit, int t) {
    for (int i = t; i < 2048; i += 256) {
        int row = i >> 4, col = (i & 15) * 8;
        int gr = base + row;
        float4 v0, v1;
        if (gr < limit) {
            v0 = __ldg((const float4*)(srcp + (size_t)gr * 128 + col));
            v1 = __ldg((const float4*)(srcp + (size_t)gr * 128 + col + 4));
        } else {
            v0 = make_float4(0.f, 0.f, 0.f, 0.f); v1 = v0;
        }
        *(uint4*)(smc + ahioff + row * RSTRIDE + col * 2) = cvt8(v0, v1);
    }
}

// edge variant: 256-bit streaming evict_first loads (protect gather tables in L2)
__device__ __forceinline__ void load_tile_stream(char* smc, int ahioff,
                                                 const float* __restrict__ srcp,
                                                 int base, int t) {
    for (int i = t; i < 2048; i += 256) {
        int row = i >> 4, col = (i & 15) * 8;
        int gr = base + row;
        float4 v0, v1;
        ldg_stream8(srcp + (size_t)gr * 128 + col, v0, v1);
        *(uint4*)(smc + ahioff + row * RSTRIDE + col * 2) = cvt8(v0, v1);
    }
}

// ---------------- mma core (ldmatrix + single fp16 pass) -----------------------
__device__ __forceinline__ void mma16816(float (&d)[4], const uint32_t (&a)[4],
                                         uint32_t b0, uint32_t b1) {
    asm("mma.sync.aligned.m16n8k16.row.col.f32.f16.f16.f32 "
        "{%0,%1,%2,%3}, {%4,%5,%6,%7}, {%8,%9}, {%0,%1,%2,%3};"
        : "+f"(d[0]), "+f"(d[1]), "+f"(d[2]), "+f"(d[3])
        : "r"(a[0]), "r"(a[1]), "r"(a[2]), "r"(a[3]), "r"(b0), "r"(b1));
}

__device__ __forceinline__ void ldmat4(uint32_t (&r)[4], uint32_t addr) {
    asm volatile("ldmatrix.sync.aligned.m8n8.x4.shared.b16 {%0,%1,%2,%3}, [%4];"
                 : "=r"(r[0]), "=r"(r[1]), "=r"(r[2]), "=r"(r[3]) : "r"(addr));
}

// block tile 128x128, warp tile 64x32
__device__ __forceinline__ void mm_one(uint32_t aBase, uint32_t bBase,
                                       int warp, int lane, float (&acc)[4][4][4]) {
    int warpm = warp & 1, warpn = warp >> 1;
    uint32_t a_addr = aBase + (uint32_t)((warpm * 64 + (lane & 15)) * RSTRIDE + ((lane >> 4) << 4));
    uint32_t b_addr = bBase + (uint32_t)((warpn * 32 + (lane & 7) + ((lane >> 4) << 3)) * RSTRIDE
                                         + (((lane >> 3) & 1) << 4));

#pragma unroll
    for (int mt = 0; mt < 4; ++mt)
#pragma unroll
        for (int nt = 0; nt < 4; ++nt)
#pragma unroll
            for (int j = 0; j < 4; ++j) acc[mt][nt][j] = 0.f;

#pragma unroll
    for (int k0 = 0; k0 < 8; ++k0) {
        uint32_t ko = k0 * 32;
        uint32_t ahi[4][4], bhi[2][4];
#pragma unroll
        for (int mt = 0; mt < 4; ++mt)
            ldmat4(ahi[mt], a_addr + mt * 16 * RSTRIDE + ko);
#pragma unroll
        for (int g = 0; g < 2; ++g)
            ldmat4(bhi[g], b_addr + g * 16 * RSTRIDE + ko);
#pragma unroll
        for (int mt = 0; mt < 4; ++mt)
#pragma unroll
            for (int nt = 0; nt < 4; ++nt)
                mma16816(acc[mt][nt], ahi[mt],
                         bhi[nt >> 1][(nt & 1) * 2], bhi[nt >> 1][(nt & 1) * 2 + 1]);
    }
}

__device__ __forceinline__ void dump_acc(char* smc, int warp, int lane,
                                         const float (&acc)[4][4][4]) {
    int warpm = warp & 1, warpn = warp >> 1;
    int q = lane >> 2, tid = lane & 3;
    float* fb = (float*)(smc + SM_FBUF);
#pragma unroll
    for (int mt = 0; mt < 4; ++mt) {
        int r = warpm * 64 + mt * 16 + q;
#pragma unroll
        for (int nt = 0; nt < 4; ++nt) {
            int c = warpn * 32 + nt * 8 + 2 * tid;
            *(float2*)&fb[r * FB_STRIDE + c]       = make_float2(acc[mt][nt][0], acc[mt][nt][1]);
            *(float2*)&fb[(r + 8) * FB_STRIDE + c] = make_float2(acc[mt][nt][2], acc[mt][nt][3]);
        }
    }
}

// ---------------- fused node GEMMs: t_src / t_dst / h_node --------------------
__global__ void __launch_bounds__(256, 1)
k_node_mma(const float* __restrict__ nfeats, const float* __restrict__ b_node) {
    extern __shared__ char smc[];
    uint32_t sbase = smem_u32(smc);
    int t = threadIdx.x, warp = t >> 5, lane = t & 31;
    int warpm = warp & 1, warpn = warp >> 1;
    int q = lane >> 2, tid = lane & 3;

    // stage the 3 B operands (slots 0: tsrc, 2: tdst, 3: hnode)
    for (int i = t; i < 2176; i += 256) {
        ((uint4*)(smc + SMN_B0))[i]                = ((const uint4*)(g_Bh + 0 * 128 * 136))[i];
        ((uint4*)(smc + SMN_B0 + AB_BYTES))[i]     = ((const uint4*)(g_Bh + 2 * 128 * 136))[i];
        ((uint4*)(smc + SMN_B0 + 2 * AB_BYTES))[i] = ((const uint4*)(g_Bh + 3 * 128 * 136))[i];
    }
    float* bias_s = (float*)(smc + SMN_BIAS);
    for (int i = t; i < 128; i += 256) bias_s[i] = __ldg(&b_node[i]);

    const int ntiles = (NN + 127) / 128;   // 391
    for (int tile = blockIdx.x; tile < ntiles; tile += gridDim.x) {
        int n0 = tile * 128;
        load_tile(smc, SMN_AHI, nfeats, n0, NN, t);
        __syncthreads();
#pragma unroll 1
        for (int mat = 0; mat < 3; ++mat) {
            __half* OUT = (mat == 0) ? g_tsrc : (mat == 1 ? g_tdst : g_hnode);
            float acc[4][4][4];
            mm_one(sbase + SMN_AHI, sbase + SMN_B0 + mat * AB_BYTES, warp, lane, acc);
            // direct fragment -> fp16 gmem store
#pragma unroll
            for (int mt = 0; mt < 4; ++mt) {
                int rr = warpm * 64 + mt * 16 + q;
#pragma unroll
                for (int nt = 0; nt < 4; ++nt) {
                    int cc = warpn * 32 + nt * 8 + 2 * tid;
                    float b0 = 0.f, b1 = 0.f;
                    if (mat == 2) { b0 = bias_s[cc]; b1 = bias_s[cc + 1]; }
                    int n1 = n0 + rr, n2 = n1 + 8;
                    if (n1 < NN)
                        *(__half2*)(OUT + (size_t)n1 * 128 + cc) =
                            __floats2half2_rn(acc[mt][nt][0] + b0, acc[mt][nt][1] + b1);
                    if (n2 < NN)
                        *(__half2*)(OUT + (size_t)n2 * 128 + cc) =
                            __floats2half2_rn(acc[mt][nt][2] + b0, acc[mt][nt][3] + b1);
                }
            }
        }
        __syncthreads();   // all reads of A done before next load_tile
    }
}

// ---------------- fused edge kernel ------------------------------------------
__global__ void __launch_bounds__(256, 2)
k_edge_mma(const float* __restrict__ efeats, const int* __restrict__ src,
           const int* __restrict__ dst, const float* __restrict__ norm,
           const float* __restrict__ bias, float* __restrict__ out2) {
    extern __shared__ char smc[];
    uint32_t sbase = smem_u32(smc);
    int t = threadIdx.x, warp = t >> 5, lane = t & 31;

    const uint4* bh = (const uint4*)(g_Bh + 1 * 128 * 136);
    for (int i = t; i < 2176; i += 256)
        ((uint4*)(smc + SM_BHI))[i] = bh[i];
    float* bias_s = (float*)(smc + SM_BIAS);
    float* ws_s   = (float*)(smc + SM_WS);
    for (int i = t; i < 128; i += 256) bias_s[i] = __ldg(&bias[i]);
    if (t < DEF) ws_s[t] = g_wsum[t];

    const int ntiles = EE / 128;   // 3125 exact
    for (int tile = blockIdx.x; tile < ntiles; tile += gridDim.x) {
        int e0 = tile * 128;
        // L2 prefetch: next A tile (64 KB = 2 x 128B lines per thread)
        int nxt = tile + gridDim.x;
        if (nxt < ntiles) {
            const char* nb = (const char*)(efeats + (size_t)nxt * 128 * 128);
            pf_l2(nb + t * 256);
            pf_l2(nb + t * 256 + 128);
        }
        // L2 prefetch: this tile's gather rows (recover any evicted table lines
        // ~3K cycles before the epilogue needs them)
        {
            int ep = e0 + (t >> 1);
            int sp  = __ldg(&src[ep]);
            int dp  = __ldg(&dst[ep]);
            int cp  = (t & 1) * 64;
            pf_l2(g_tsrc + (size_t)sp * 128 + cp);
            pf_l2(g_tdst + (size_t)dp * 128 + cp);
        }
        load_tile_stream(smc, SM_AHI, efeats, e0, t);
        __syncthreads();
        float acc[4][4][4];
        mm_one(sbase + SM_AHI, sbase + SM_BHI, warp, lane, acc);
        __syncthreads();
        dump_acc(smc, warp, lane, acc);
        __syncthreads();

        // epilogue: 2 threads per edge row (halves of 128 cols = 4 heads each)
        int e = e0 + (t >> 1);
        int half = t & 1;
        int c0 = half * 64, h0 = half * 4;
        int s  = __ldg(&src[e]);
        int dd = __ldg(&dst[e]);
        float nrm = __ldg(&norm[e]);
        const float* frow = (float*)(smc + SM_FBUF) + (t >> 1) * FB_STRIDE + c0;
        const uint4* tsp = (const uint4*)(g_tsrc + (size_t)s * 128 + c0);
        const uint4* tdp = (const uint4*)(g_tdst + (size_t)dd * 128 + c0);

        float pd[16];
#pragma unroll
        for (int d = 0; d < 16; ++d) pd[d] = 0.f;
        float ex[4], exn[4];
#pragma unroll
        for (int hl = 0; hl < 4; ++hl) {
            uint4 sa0 = __ldg(tsp + hl * 2), sa1 = __ldg(tsp + hl * 2 + 1);
            uint4 da0 = __ldg(tdp + hl * 2), da1 = __ldg(tdp + hl * 2 + 1);
            uint32_t sw[8] = {sa0.x, sa0.y, sa0.z, sa0.w, sa1.x, sa1.y, sa1.z, sa1.w};
            uint32_t dw[8] = {da0.x, da0.y, da0.z, da0.w, da1.x, da1.y, da1.z, da1.w};
            float lgv = 0.f;
#pragma unroll
            for (int j = 0; j < 4; ++j) {
                float4 dv = *(const float4*)(frow + hl * 16 + j * 4);
                float2 s01 = h2f2(sw[j * 2]), s23 = h2f2(sw[j * 2 + 1]);
                float2 d01 = h2f2(dw[j * 2]), d23 = h2f2(dw[j * 2 + 1]);
                int cb = c0 + hl * 16 + j * 4;
                float v0 = dv.x + s01.x + d01.x;
                float v1 = dv.y + s01.y + d01.y;
                float v2 = dv.z + s23.x + d23.x;
                float v3 = dv.w + s23.y + d23.y;
                v0 = (v0 > 0.f) ? v0 : 0.01f * v0;
                v1 = (v1 > 0.f) ? v1 : 0.01f * v1;
                v2 = (v2 > 0.f) ? v2 : 0.01f * v2;
                v3 = (v3 > 0.f) ? v3 : 0.01f * v3;
                v0 += bias_s[cb];
                v1 += bias_s[cb + 1];
                v2 += bias_s[cb + 2];
                v3 += bias_s[cb + 3];
                pd[j * 4]     += v0;
                pd[j * 4 + 1] += v1;
                pd[j * 4 + 2] += v2;
                pd[j * 4 + 3] += v3;
                lgv += v0 * ws_s[j * 4] + v1 * ws_s[j * 4 + 1]
                     + v2 * ws_s[j * 4 + 2] + v3 * ws_s[j * 4 + 3];
            }
            ex[hl]  = __expf(lgv);
            exn[hl] = ex[hl] * nrm;
        }
#pragma unroll
        for (int d = 0; d < 16; ++d) pd[d] += __shfl_xor_sync(0xffffffffu, pd[d], 1);
        if (!half) {
            stg_stream8(out2 + (size_t)e * DEF, pd);
            stg_stream8(out2 + (size_t)e * DEF + 8, pd + 8);
        }
        ((float4*)g_a)[(size_t)e * 2 + half] = make_float4(exn[0], exn[1], exn[2], exn[3]);
#pragma unroll
        for (int hl = 0; hl < 4; ++hl)
            atomicAdd(&g_den[(size_t)dd * NHEAD + h0 + hl], ex[hl]);
        __syncthreads();
    }
}

// ---------------- message passing (coalesced + shuffle reduce) ----------------
// warp = 2 edges; lane t16 loads one uint4 (head h = t16>>1, dims (t16&1)*8..+7)
__global__ void k_msg(const int* __restrict__ src, const int* __restrict__ dst,
                      float* __restrict__ out1) {
    int gid = blockIdx.x * blockDim.x + threadIdx.x;
    int lane = gid & 31;
    int e = (gid >> 5) * 2 + (lane >> 4);
    if (e >= EE) return;                 // grid exact: never diverges
    int t16 = lane & 15;
    int h = t16 >> 1;
    int s  = __ldg(&src[e]);
    int dd = __ldg(&dst[e]);
    float w = __fdividef(__ldg(&g_a[(size_t)e * NHEAD + h]),
                         __ldg(&g_den[(size_t)dd * NHEAD + h]));
    uint4 hv = __ldg((const uint4*)(g_hnode + (size_t)s * 128) + t16);
    uint32_t hw[4] = {hv.x, hv.y, hv.z, hv.w};
    float p[8];
#pragma unroll
    for (int j = 0; j < 4; ++j) {
        float2 f = h2f2(hw[j]);
        p[2 * j]     = w * f.x;
        p[2 * j + 1] = w * f.y;
    }
    // reduce over the 3 head bits (lane bits 1..3)
#pragma unroll
    for (int m = 2; m <= 8; m <<= 1)
#pragma unroll
        for (int j = 0; j < 8; ++j)
            p[j] += __shfl_xor_sync(0xffffffffu, p[j], m);
    if ((lane & 14) == 0) {
        int dbase = (t16 & 1) * 8;
#pragma unroll
        for (int j = 0; j < 8; ++j)
            atomicAdd(&out1[(size_t)dd * DNF + dbase + j], p[j]);
    }
}

// ---------------- launch ------------------------------------------------------
extern "C" void kernel_launch(void* const* d_in, const int* in_sizes, int n_in,
                              void* d_out, int out_size) {
    const float* nfeats  = (const float*)d_in[0];
    const float* efeats  = (const float*)d_in[1];
    const float* norm    = (const float*)d_in[2];
    const int*   src     = (const int*)d_in[3];
    const int*   dst     = (const int*)d_in[4];
    const float* W_ni    = (const float*)d_in[5];
    const float* W_nj    = (const float*)d_in[6];
    const float* W_fij   = (const float*)d_in[7];
    const float* W_edges = (const float*)d_in[8];
    const float* W_attn  = (const float*)d_in[9];
    const float* bias    = (const float*)d_in[10];
    const float* W_node  = (const float*)d_in[11];
    const float* b_node  = (const float*)d_in[12];

    float* out1 = (float*)d_out;
    float* out2 = out1 + (size_t)NN * DNF;

    cudaFuncSetAttribute(k_node_mma, cudaFuncAttributeMaxDynamicSharedMemorySize, SMN_TOTAL);
    cudaFuncSetAttribute(k_edge_mma, cudaFuncAttributeMaxDynamicSharedMemorySize, SM_TOTAL);

    k_init<<<3125, 256>>>(out1);
    k_wb<<<dim3(128, 4), 128>>>(W_edges, W_ni, W_nj, W_fij, W_node, W_attn);
    k_node_mma<<<148, 256, SMN_TOTAL>>>(nfeats, b_node);
    k_edge_mma<<<296, 256, SM_TOTAL>>>(efeats, src, dst, norm, bias, out2);
    k_msg<<<(EE / 2) * 32 / 256, 256>>>(src, dst, out1);
}

// round 13
// speedup vs baseline: 1.9998x; 1.0640x over previous
#include <cuda_runtime.h>
#include <cuda_fp16.h>
#include <cstring>
#include <cstdint>

#define NN 50000
#define EE 400000
#define NHEAD 8
#define DEF 16
#define DNF 16

// ---------------- device global scratch ------------------------------------
__device__ float g_wsum[DEF];
// B operands as fp16 [n][k], row stride 136 (slot 0:tsrc 1:edge 2:tdst 3:hnode)
__device__ __half g_Bh[4 * 128 * 136];
__device__ __half g_tsrc[NN * 128];
__device__ __half g_tdst[NN * 128];
__device__ __half g_hnode[NN * 128];
__device__ float g_a[EE * NHEAD];    // exp(logit) * norm
__device__ float g_den[NN * NHEAD];  // sum of raw exp(logit)

// ---------------- smem layouts (bytes) ---------------------------------------
#define RSTRIDE 272                 // 136 fp16 per row
#define AB_BYTES (128 * RSTRIDE)    // 34816

// edge kernel: bias/ws | A | B | fbuf(fp16) -- A and fbuf DISJOINT
#define SM_BIAS 0
#define SM_WS   512
#define SM_A    1024
#define SM_BHI  (SM_A + AB_BYTES)       // 35840
#define SM_FB   (SM_BHI + AB_BYTES)     // 70656
#define SM_TOTAL (SM_FB + AB_BYTES)     // 105472  (2 CTAs/SM)

// fused node kernel layout
#define SMN_BIAS 0
#define SMN_AHI  1024
#define SMN_B0   (SMN_AHI + AB_BYTES)           // 35840
#define SMN_TOTAL (SMN_B0 + 3 * AB_BYTES)       // 140288

// ---------------- helpers ------------------------------------------------------
__device__ __forceinline__ uint32_t smem_u32(const void* p) {
    uint32_t a;
    asm("{ .reg .u64 t; cvta.to.shared.u64 t, %1; cvt.u32.u64 %0, t; }" : "=r"(a) : "l"(p));
    return a;
}
__device__ __forceinline__ float2 h2f2(uint32_t u) {
    __half2 h;
    memcpy(&h, &u, 4);
    return __half22float2(h);
}
// 256-bit streaming load (this toolchain requires v8.b32 for L2::evict_first)
__device__ __forceinline__ void ldg_stream8(const float* p, float4& v0, float4& v1) {
    uint32_t r0, r1, r2, r3, r4, r5, r6, r7;
    asm volatile("ld.global.nc.L2::evict_first.v8.b32 {%0,%1,%2,%3,%4,%5,%6,%7}, [%8];"
                 : "=r"(r0), "=r"(r1), "=r"(r2), "=r"(r3),
                   "=r"(r4), "=r"(r5), "=r"(r6), "=r"(r7) : "l"(p));
    v0.x = __uint_as_float(r0); v0.y = __uint_as_float(r1);
    v0.z = __uint_as_float(r2); v0.w = __uint_as_float(r3);
    v1.x = __uint_as_float(r4); v1.y = __uint_as_float(r5);
    v1.z = __uint_as_float(r6); v1.w = __uint_as_float(r7);
}
__device__ __forceinline__ void stg_stream8(float* p, const float* v) {
    asm volatile("st.global.L2::evict_first.v8.b32 [%0], {%1,%2,%3,%4,%5,%6,%7,%8};"
                 :: "l"(p),
                    "r"(__float_as_uint(v[0])), "r"(__float_as_uint(v[1])),
                    "r"(__float_as_uint(v[2])), "r"(__float_as_uint(v[3])),
                    "r"(__float_as_uint(v[4])), "r"(__float_as_uint(v[5])),
                    "r"(__float_as_uint(v[6])), "r"(__float_as_uint(v[7])));
}
__device__ __forceinline__ void pf_l2(const void* p) {
    asm volatile("prefetch.global.L2 [%0];" :: "l"(p));
}

// ---------------- small kernels ----------------------------------------------
__global__ void k_init(float* __restrict__ out1) {
    int i = blockIdx.x * blockDim.x + threadIdx.x;
    if (i < NN * NHEAD) g_den[i] = 0.f;
    if (i < NN * DNF)   out1[i] = 0.f;
}

// fused: combined weights -> fp16 B operands directly
__global__ void k_wb(const float* __restrict__ W_edges,
                     const float* __restrict__ W_ni,
                     const float* __restrict__ W_nj,
                     const float* __restrict__ W_fij,
                     const float* __restrict__ W_node,
                     const float* __restrict__ W_attn) {
    int k = blockIdx.x, c = threadIdx.x, m = blockIdx.y;
    float acc = 0.f;
    if (m == 0) {
        for (int j = 0; j < 128; ++j) acc += W_edges[c * 384 + j] * W_ni[j * 128 + k];
    } else if (m == 1) {
        for (int j = 0; j < 128; ++j) acc += W_edges[c * 384 + 128 + j] * W_fij[j * 128 + k];
    } else if (m == 2) {
        for (int j = 0; j < 128; ++j) acc += W_edges[c * 384 + 256 + j] * W_nj[j * 128 + k];
    } else {
        acc = W_node[c * 128 + k];
        if (k == 0 && c < DEF) {
            float s = 0.f;
            for (int h = 0; h < NHEAD; ++h) s += W_attn[h * DEF + c];
            g_wsum[c] = s;
        }
    }
    g_Bh[m * 128 * 136 + c * 136 + k] = __float2half_rn(acc);
}

// ---------------- fp32 -> fp16 tile stage -------------------------------------
__device__ __forceinline__ uint4 cvt8(const float4 v0, const float4 v1) {
    unsigned hu[4];
    __half2 h0 = __floats2half2_rn(v0.x, v0.y);
    __half2 h1 = __floats2half2_rn(v0.z, v0.w);
    __half2 h2 = __floats2half2_rn(v1.x, v1.y);
    __half2 h3 = __floats2half2_rn(v1.z, v1.w);
    memcpy(&hu[0], &h0, 4);
    memcpy(&hu[1], &h1, 4);
    memcpy(&hu[2], &h2, 4);
    memcpy(&hu[3], &h3, 4);
    return make_uint4(hu[0], hu[1], hu[2], hu[3]);
}

// node variant: normal loads (nfeats re-used across 3 mats in-kernel)
__device__ __forceinline__ void load_tile(char* smc, int ahioff,
                                          const float* __restrict__ srcp,
                                          int base, int limit, int t) {
    for (int i = t; i < 2048; i += 256) {
        int row = i >> 4, col = (i & 15) * 8;
        int gr = base + row;
        float4 v0, v1;
        if (gr < limit) {
            v0 = __ldg((const float4*)(srcp + (size_t)gr * 128 + col));
            v1 = __ldg((const float4*)(srcp + (size_t)gr * 128 + col + 4));
        } else {
            v0 = make_float4(0.f, 0.f, 0.f, 0.f); v1 = v0;
        }
        *(uint4*)(smc + ahioff + row * RSTRIDE + col * 2) = cvt8(v0, v1);
    }
}

// edge variant: 256-bit streaming evict_first loads (protect gather tables in L2)
__device__ __forceinline__ void load_tile_stream(char* smc, int ahioff,
                                                 const float* __restrict__ srcp,
                                                 int base, int t) {
    for (int i = t; i < 2048; i += 256) {
        int row = i >> 4, col = (i & 15) * 8;
        int gr = base + row;
        float4 v0, v1;
        ldg_stream8(srcp + (size_t)gr * 128 + col, v0, v1);
        *(uint4*)(smc + ahioff + row * RSTRIDE + col * 2) = cvt8(v0, v1);
    }
}

// ---------------- mma core (ldmatrix + single fp16 pass) -----------------------
__device__ __forceinline__ void mma16816(float (&d)[4], const uint32_t (&a)[4],
                                         uint32_t b0, uint32_t b1) {
    asm("mma.sync.aligned.m16n8k16.row.col.f32.f16.f16.f32 "
        "{%0,%1,%2,%3}, {%4,%5,%6,%7}, {%8,%9}, {%0,%1,%2,%3};"
        : "+f"(d[0]), "+f"(d[1]), "+f"(d[2]), "+f"(d[3])
        : "r"(a[0]), "r"(a[1]), "r"(a[2]), "r"(a[3]), "r"(b0), "r"(b1));
}

__device__ __forceinline__ void ldmat4(uint32_t (&r)[4], uint32_t addr) {
    asm volatile("ldmatrix.sync.aligned.m8n8.x4.shared.b16 {%0,%1,%2,%3}, [%4];"
                 : "=r"(r[0]), "=r"(r[1]), "=r"(r[2]), "=r"(r[3]) : "r"(addr));
}

// block tile 128x128, warp tile 64x32
__device__ __forceinline__ void mm_one(uint32_t aBase, uint32_t bBase,
                                       int warp, int lane, float (&acc)[4][4][4]) {
    int warpm = warp & 1, warpn = warp >> 1;
    uint32_t a_addr = aBase + (uint32_t)((warpm * 64 + (lane & 15)) * RSTRIDE + ((lane >> 4) << 4));
    uint32_t b_addr = bBase + (uint32_t)((warpn * 32 + (lane & 7) + ((lane >> 4) << 3)) * RSTRIDE
                                         + (((lane >> 3) & 1) << 4));

#pragma unroll
    for (int mt = 0; mt < 4; ++mt)
#pragma unroll
        for (int nt = 0; nt < 4; ++nt)
#pragma unroll
            for (int j = 0; j < 4; ++j) acc[mt][nt][j] = 0.f;

#pragma unroll
    for (int k0 = 0; k0 < 8; ++k0) {
        uint32_t ko = k0 * 32;
        uint32_t ahi[4][4], bhi[2][4];
#pragma unroll
        for (int mt = 0; mt < 4; ++mt)
            ldmat4(ahi[mt], a_addr + mt * 16 * RSTRIDE + ko);
#pragma unroll
        for (int g = 0; g < 2; ++g)
            ldmat4(bhi[g], b_addr + g * 16 * RSTRIDE + ko);
#pragma unroll
        for (int mt = 0; mt < 4; ++mt)
#pragma unroll
            for (int nt = 0; nt < 4; ++nt)
                mma16816(acc[mt][nt], ahi[mt],
                         bhi[nt >> 1][(nt & 1) * 2], bhi[nt >> 1][(nt & 1) * 2 + 1]);
    }
}

// fp16 accumulator staging (halves STS/LDS traffic; fbuf fits A-sized buffer)
__device__ __forceinline__ void dump_acc16(char* smc, int warp, int lane,
                                           const float (&acc)[4][4][4]) {
    int warpm = warp & 1, warpn = warp >> 1;
    int q = lane >> 2, tid = lane & 3;
    __half* fb = (__half*)(smc + SM_FB);
#pragma unroll
    for (int mt = 0; mt < 4; ++mt) {
        int r = warpm * 64 + mt * 16 + q;
#pragma unroll
        for (int nt = 0; nt < 4; ++nt) {
            int c = warpn * 32 + nt * 8 + 2 * tid;
            *(__half2*)&fb[r * 136 + c]       = __floats2half2_rn(acc[mt][nt][0], acc[mt][nt][1]);
            *(__half2*)&fb[(r + 8) * 136 + c] = __floats2half2_rn(acc[mt][nt][2], acc[mt][nt][3]);
        }
    }
}

// ---------------- fused node GEMMs: t_src / t_dst / h_node --------------------
__global__ void __launch_bounds__(256, 1)
k_node_mma(const float* __restrict__ nfeats, const float* __restrict__ b_node) {
    extern __shared__ char smc[];
    uint32_t sbase = smem_u32(smc);
    int t = threadIdx.x, warp = t >> 5, lane = t & 31;
    int warpm = warp & 1, warpn = warp >> 1;
    int q = lane >> 2, tid = lane & 3;

    // stage the 3 B operands (slots 0: tsrc, 2: tdst, 3: hnode)
    for (int i = t; i < 2176; i += 256) {
        ((uint4*)(smc + SMN_B0))[i]                = ((const uint4*)(g_Bh + 0 * 128 * 136))[i];
        ((uint4*)(smc + SMN_B0 + AB_BYTES))[i]     = ((const uint4*)(g_Bh + 2 * 128 * 136))[i];
        ((uint4*)(smc + SMN_B0 + 2 * AB_BYTES))[i] = ((const uint4*)(g_Bh + 3 * 128 * 136))[i];
    }
    float* bias_s = (float*)(smc + SMN_BIAS);
    for (int i = t; i < 128; i += 256) bias_s[i] = __ldg(&b_node[i]);

    const int ntiles = (NN + 127) / 128;   // 391
    for (int tile = blockIdx.x; tile < ntiles; tile += gridDim.x) {
        int n0 = tile * 128;
        load_tile(smc, SMN_AHI, nfeats, n0, NN, t);
        __syncthreads();
#pragma unroll 1
        for (int mat = 0; mat < 3; ++mat) {
            __half* OUT = (mat == 0) ? g_tsrc : (mat == 1 ? g_tdst : g_hnode);
            float acc[4][4][4];
            mm_one(sbase + SMN_AHI, sbase + SMN_B0 + mat * AB_BYTES, warp, lane, acc);
            // direct fragment -> fp16 gmem store
#pragma unroll
            for (int mt = 0; mt < 4; ++mt) {
                int rr = warpm * 64 + mt * 16 + q;
#pragma unroll
                for (int nt = 0; nt < 4; ++nt) {
                    int cc = warpn * 32 + nt * 8 + 2 * tid;
                    float b0 = 0.f, b1 = 0.f;
                    if (mat == 2) { b0 = bias_s[cc]; b1 = bias_s[cc + 1]; }
                    int n1 = n0 + rr, n2 = n1 + 8;
                    if (n1 < NN)
                        *(__half2*)(OUT + (size_t)n1 * 128 + cc) =
                            __floats2half2_rn(acc[mt][nt][0] + b0, acc[mt][nt][1] + b1);
                    if (n2 < NN)
                        *(__half2*)(OUT + (size_t)n2 * 128 + cc) =
                            __floats2half2_rn(acc[mt][nt][2] + b0, acc[mt][nt][3] + b1);
                }
            }
        }
        __syncthreads();   // all reads of A done before next load_tile
    }
}

// ---------------- fused edge kernel (pipelined stage||epilogue) ----------------
__device__ __forceinline__ void edge_epilogue(char* smc, int e0, int t,
                                              const int* __restrict__ src,
                                              const int* __restrict__ dst,
                                              const float* __restrict__ norm,
                                              float* __restrict__ out2) {
    const float* bias_s = (const float*)(smc + SM_BIAS);
    const float* ws_s   = (const float*)(smc + SM_WS);
    int e = e0 + (t >> 1);
    int half = t & 1;
    int c0 = half * 64, h0 = half * 4;
    int s  = __ldg(&src[e]);
    int dd = __ldg(&dst[e]);
    float nrm = __ldg(&norm[e]);
    const uint4* frow = (const uint4*)(smc + SM_FB + (t >> 1) * RSTRIDE + c0 * 2);
    const uint4* tsp = (const uint4*)(g_tsrc + (size_t)s * 128 + c0);
    const uint4* tdp = (const uint4*)(g_tdst + (size_t)dd * 128 + c0);

    float pd[16];
#pragma unroll
    for (int d = 0; d < 16; ++d) pd[d] = 0.f;
    float ex[4], exn[4];
#pragma unroll
    for (int hl = 0; hl < 4; ++hl) {
        uint4 fv0 = frow[hl * 2],     fv1 = frow[hl * 2 + 1];
        uint4 sa0 = __ldg(tsp + hl * 2), sa1 = __ldg(tsp + hl * 2 + 1);
        uint4 da0 = __ldg(tdp + hl * 2), da1 = __ldg(tdp + hl * 2 + 1);
        uint32_t fw[8] = {fv0.x, fv0.y, fv0.z, fv0.w, fv1.x, fv1.y, fv1.z, fv1.w};
        uint32_t sw[8] = {sa0.x, sa0.y, sa0.z, sa0.w, sa1.x, sa1.y, sa1.z, sa1.w};
        uint32_t dw[8] = {da0.x, da0.y, da0.z, da0.w, da1.x, da1.y, da1.z, da1.w};
        float lgv = 0.f;
#pragma unroll
        for (int j = 0; j < 4; ++j) {
            float2 f01 = h2f2(fw[j * 2]), f23 = h2f2(fw[j * 2 + 1]);
            float2 s01 = h2f2(sw[j * 2]), s23 = h2f2(sw[j * 2 + 1]);
            float2 d01 = h2f2(dw[j * 2]), d23 = h2f2(dw[j * 2 + 1]);
            int cb = c0 + hl * 16 + j * 4;
            float v0 = f01.x + s01.x + d01.x;
            float v1 = f01.y + s01.y + d01.y;
            float v2 = f23.x + s23.x + d23.x;
            float v3 = f23.y + s23.y + d23.y;
            v0 = (v0 > 0.f) ? v0 : 0.01f * v0;
            v1 = (v1 > 0.f) ? v1 : 0.01f * v1;
            v2 = (v2 > 0.f) ? v2 : 0.01f * v2;
            v3 = (v3 > 0.f) ? v3 : 0.01f * v3;
            v0 += bias_s[cb];
            v1 += bias_s[cb + 1];
            v2 += bias_s[cb + 2];
            v3 += bias_s[cb + 3];
            pd[j * 4]     += v0;
            pd[j * 4 + 1] += v1;
            pd[j * 4 + 2] += v2;
            pd[j * 4 + 3] += v3;
            lgv += v0 * ws_s[j * 4] + v1 * ws_s[j * 4 + 1]
                 + v2 * ws_s[j * 4 + 2] + v3 * ws_s[j * 4 + 3];
        }
        ex[hl]  = __expf(lgv);
        exn[hl] = ex[hl] * nrm;
    }
#pragma unroll
    for (int d = 0; d < 16; ++d) pd[d] += __shfl_xor_sync(0xffffffffu, pd[d], 1);
    if (!half) {
        stg_stream8(out2 + (size_t)e * DEF, pd);
        stg_stream8(out2 + (size_t)e * DEF + 8, pd + 8);
    }
    ((float4*)g_a)[(size_t)e * 2 + half] = make_float4(exn[0], exn[1], exn[2], exn[3]);
#pragma unroll
    for (int hl = 0; hl < 4; ++hl)
        atomicAdd(&g_den[(size_t)dd * NHEAD + h0 + hl], ex[hl]);
}

__global__ void __launch_bounds__(256, 2)
k_edge_mma(const float* __restrict__ efeats, const int* __restrict__ src,
           const int* __restrict__ dst, const float* __restrict__ norm,
           const float* __restrict__ bias, float* __restrict__ out2) {
    extern __shared__ char smc[];
    uint32_t sbase = smem_u32(smc);
    int t = threadIdx.x, warp = t >> 5, lane = t & 31;

    const uint4* bh = (const uint4*)(g_Bh + 1 * 128 * 136);
    for (int i = t; i < 2176; i += 256)
        ((uint4*)(smc + SM_BHI))[i] = bh[i];
    float* bias_s = (float*)(smc + SM_BIAS);
    float* ws_s   = (float*)(smc + SM_WS);
    for (int i = t; i < 128; i += 256) bias_s[i] = __ldg(&bias[i]);
    if (t < DEF) ws_s[t] = g_wsum[t];

    const int ntiles = EE / 128;   // 3125 exact
    int tile = blockIdx.x;
    // prologue: stage first tile (grid 296 << 3125, always valid)
    load_tile_stream(smc, SM_A, efeats, tile * 128, t);
    __syncthreads();

    for (; tile < ntiles; tile += gridDim.x) {
        int e0 = tile * 128;
        // L2 prefetch two strides ahead (stage of tile+stride is this iteration)
        int nxt2 = tile + 2 * gridDim.x;
        if (nxt2 < ntiles) {
            const char* nb = (const char*)(efeats + (size_t)nxt2 * 128 * 128);
            pf_l2(nb + t * 256);
            pf_l2(nb + t * 256 + 128);
        }
        float acc[4][4][4];
        mm_one(sbase + SM_A, sbase + SM_BHI, warp, lane, acc);
        __syncthreads();          // A reads done; prev epilogue's fbuf reads done
        dump_acc16(smc, warp, lane, acc);
        __syncthreads();          // fbuf visible to all

        // overlap region: stage next tile (A dead)  ||  epilogue this tile (fbuf)
        {
            // gather-row L2 prefetch for this tile's epilogue
            int ep = e0 + (t >> 1);
            int sp  = __ldg(&src[ep]);
            int dp  = __ldg(&dst[ep]);
            int cp  = (t & 1) * 64;
            pf_l2(g_tsrc + (size_t)sp * 128 + cp);
            pf_l2(g_tdst + (size_t)dp * 128 + cp);
        }
        int nxt = tile + gridDim.x;
        if (nxt < ntiles)
            load_tile_stream(smc, SM_A, efeats, nxt * 128, t);
        edge_epilogue(smc, e0, t, src, dst, norm, out2);
        __syncthreads();          // stage complete + fbuf reads done
    }
}

// ---------------- message passing (coalesced + shuffle reduce) ----------------
// warp = 2 edges; lane t16 loads one uint4 (head h = t16>>1, dims (t16&1)*8..+7)
__global__ void k_msg(const int* __restrict__ src, const int* __restrict__ dst,
                      float* __restrict__ out1) {
    int gid = blockIdx.x * blockDim.x + threadIdx.x;
    int lane = gid & 31;
    int e = (gid >> 5) * 2 + (lane >> 4);
    if (e >= EE) return;                 // grid exact: never diverges
    int t16 = lane & 15;
    int h = t16 >> 1;
    int s  = __ldg(&src[e]);
    int dd = __ldg(&dst[e]);
    float w = __fdividef(__ldg(&g_a[(size_t)e * NHEAD + h]),
                         __ldg(&g_den[(size_t)dd * NHEAD + h]));
    uint4 hv = __ldg((const uint4*)(g_hnode + (size_t)s * 128) + t16);
    uint32_t hw[4] = {hv.x, hv.y, hv.z, hv.w};
    float p[8];
#pragma unroll
    for (int j = 0; j < 4; ++j) {
        float2 f = h2f2(hw[j]);
        p[2 * j]     = w * f.x;
        p[2 * j + 1] = w * f.y;
    }
    // reduce over the 3 head bits (lane bits 1..3)
#pragma unroll
    for (int m = 2; m <= 8; m <<= 1)
#pragma unroll
        for (int j = 0; j < 8; ++j)
            p[j] += __shfl_xor_sync(0xffffffffu, p[j], m);
    if ((lane & 14) == 0) {
        int dbase = (t16 & 1) * 8;
#pragma unroll
        for (int j = 0; j < 8; ++j)
            atomicAdd(&out1[(size_t)dd * DNF + dbase + j], p[j]);
    }
}

// ---------------- launch ------------------------------------------------------
extern "C" void kernel_launch(void* const* d_in, const int* in_sizes, int n_in,
                              void* d_out, int out_size) {
    const float* nfeats  = (const float*)d_in[0];
    const float* efeats  = (const float*)d_in[1];
    const float* norm    = (const float*)d_in[2];
    const int*   src     = (const int*)d_in[3];
    const int*   dst     = (const int*)d_in[4];
    const float* W_ni    = (const float*)d_in[5];
    const float* W_nj    = (const float*)d_in[6];
    const float* W_fij   = (const float*)d_in[7];
    const float* W_edges = (const float*)d_in[8];
    const float* W_attn  = (const float*)d_in[9];
    const float* bias    = (const float*)d_in[10];
    const float* W_node  = (const float*)d_in[11];
    const float* b_node  = (const float*)d_in[12];

    float* out1 = (float*)d_out;
    float* out2 = out1 + (size_t)NN * DNF;

    cudaFuncSetAttribute(k_node_mma, cudaFuncAttributeMaxDynamicSharedMemorySize, SMN_TOTAL);
    cudaFuncSetAttribute(k_edge_mma, cudaFuncAttributeMaxDynamicSharedMemorySize, SM_TOTAL);

    k_init<<<3125, 256>>>(out1);
    k_wb<<<dim3(128, 4), 128>>>(W_edges, W_ni, W_nj, W_fij, W_node, W_attn);
    k_node_mma<<<148, 256, SMN_TOTAL>>>(nfeats, b_node);
    k_edge_mma<<<296, 256, SM_TOTAL>>>(efeats, src, dst, norm, bias, out2);
    k_msg<<<(EE / 2) * 32 / 256, 256>>>(src, dst, out1);
}